// round 7
// baseline (speedup 1.0000x reference)
#include <cuda_runtime.h>
#include <math.h>

#define OBJ_DIM 256
#define GRU3    768
#define MAX_OBJ  50000
#define MAX_EVT  100000
#define MAX_EDGE 500000
#define MAX_MAIN 25000

// ---------------- device scratch (allocation-free per harness rules) --------
__device__ float g_proj[(size_t)MAX_EVT * OBJ_DIM];   // relu(event_X @ Wp^T + bp)
__device__ float g_sums[(size_t)MAX_OBJ * OBJ_DIM];   // scatter sums -> profile
__device__ float g_cnt[MAX_OBJ];
__device__ int   g_mask[MAX_OBJ];
__device__ int   g_list[MAX_MAIN];                    // compacted unique main objs
__device__ int   g_count;
__device__ float g_gi[(size_t)MAX_MAIN * GRU3];
__device__ float g_gh[(size_t)MAX_MAIN * GRU3];

// ---------------- small utility kernels -------------------------------------
__global__ void zero_kernel(int nObj) {
    int i = blockIdx.x * blockDim.x + threadIdx.x;
    if (i < nObj * 64) {
        ((float4*)g_sums)[i] = make_float4(0.f, 0.f, 0.f, 0.f);
    }
    if (i < nObj) { g_cnt[i] = 0.f; g_mask[i] = 0; }
    if (i == 0)   g_count = 0;
}

__global__ void mask_kernel(const int* __restrict__ main_idx, int nMain) {
    int i = blockIdx.x * blockDim.x + threadIdx.x;
    if (i < nMain) g_mask[main_idx[i]] = 1;
}

__global__ void compact_kernel(int nObj) {
    int i = blockIdx.x * blockDim.x + threadIdx.x;
    if (i < nObj && g_mask[i]) {
        int p = atomicAdd(&g_count, 1);
        g_list[p] = i;
    }
}

// ---------------- tiled SGEMM: C[M,N] = act(A[M,K] @ W[N,K]^T + bias) -------
// BM=BN=64, BK=32, 256 threads, 4x4 per thread.
// useList: gather A rows through g_list; useCount: M = g_count (device-side).
#define BM 64
#define BN 64
#define BK 32

__global__ __launch_bounds__(256, 2) void gemm_kernel(
    const float* __restrict__ A, const float* __restrict__ W,
    const float* __restrict__ bias, float* __restrict__ C,
    int M, int N, int K, int useList, int useCount, int doRelu)
{
    int Meff = useCount ? g_count : M;
    int row0 = blockIdx.y * BM;
    if (row0 >= Meff) return;
    int n0 = blockIdx.x * BN;

    __shared__ __align__(16) float As[BK][BM + 4];
    __shared__ __align__(16) float Ws[BK][BN + 4];

    int t  = threadIdx.x;
    int ml = t >> 3;             // 0..31 (loader row)
    int k4 = (t & 7) << 2;       // 0,4,...,28
    int tx = t & 15, ty = t >> 4;

    float acc[4][4];
#pragma unroll
    for (int i = 0; i < 4; i++)
#pragma unroll
        for (int j = 0; j < 4; j++) acc[i][j] = 0.f;

    // resolve the two A rows this thread loads
    long ar0 = -1, ar1 = -1;
    int grow0 = row0 + ml, grow1 = row0 + ml + 32;
    if (grow0 < Meff) ar0 = useList ? (long)g_list[grow0] : (long)grow0;
    if (grow1 < Meff) ar1 = useList ? (long)g_list[grow1] : (long)grow1;

    const float* Wr0 = W + (size_t)(n0 + ml) * K;
    const float* Wr1 = W + (size_t)(n0 + ml + 32) * K;

    for (int k0 = 0; k0 < K; k0 += BK) {
        float4 a0 = make_float4(0.f, 0.f, 0.f, 0.f);
        float4 a1 = make_float4(0.f, 0.f, 0.f, 0.f);
        if (ar0 >= 0) a0 = *(const float4*)(A + ar0 * (long)K + k0 + k4);
        if (ar1 >= 0) a1 = *(const float4*)(A + ar1 * (long)K + k0 + k4);
        float4 w0 = *(const float4*)(Wr0 + k0 + k4);
        float4 w1 = *(const float4*)(Wr1 + k0 + k4);

        __syncthreads();
        As[k4 + 0][ml] = a0.x; As[k4 + 1][ml] = a0.y;
        As[k4 + 2][ml] = a0.z; As[k4 + 3][ml] = a0.w;
        As[k4 + 0][ml + 32] = a1.x; As[k4 + 1][ml + 32] = a1.y;
        As[k4 + 2][ml + 32] = a1.z; As[k4 + 3][ml + 32] = a1.w;
        Ws[k4 + 0][ml] = w0.x; Ws[k4 + 1][ml] = w0.y;
        Ws[k4 + 2][ml] = w0.z; Ws[k4 + 3][ml] = w0.w;
        Ws[k4 + 0][ml + 32] = w1.x; Ws[k4 + 1][ml + 32] = w1.y;
        Ws[k4 + 2][ml + 32] = w1.z; Ws[k4 + 3][ml + 32] = w1.w;
        __syncthreads();

#pragma unroll
        for (int k = 0; k < BK; k++) {
            float4 av = *(const float4*)&As[k][ty << 2];
            float4 bv = *(const float4*)&Ws[k][tx << 2];
            acc[0][0] += av.x * bv.x; acc[0][1] += av.x * bv.y;
            acc[0][2] += av.x * bv.z; acc[0][3] += av.x * bv.w;
            acc[1][0] += av.y * bv.x; acc[1][1] += av.y * bv.y;
            acc[1][2] += av.y * bv.z; acc[1][3] += av.y * bv.w;
            acc[2][0] += av.z * bv.x; acc[2][1] += av.z * bv.y;
            acc[2][2] += av.z * bv.z; acc[2][3] += av.z * bv.w;
            acc[3][0] += av.w * bv.x; acc[3][1] += av.w * bv.y;
            acc[3][2] += av.w * bv.z; acc[3][3] += av.w * bv.w;
        }
    }

    float4 bb = *(const float4*)(bias + n0 + (tx << 2));
#pragma unroll
    for (int i = 0; i < 4; i++) {
        int m = row0 + (ty << 2) + i;
        if (m < Meff) {
            float4 v;
            v.x = acc[i][0] + bb.x; v.y = acc[i][1] + bb.y;
            v.z = acc[i][2] + bb.z; v.w = acc[i][3] + bb.w;
            if (doRelu) {
                v.x = fmaxf(v.x, 0.f); v.y = fmaxf(v.y, 0.f);
                v.z = fmaxf(v.z, 0.f); v.w = fmaxf(v.w, 0.f);
            }
            *(float4*)(C + (size_t)m * N + n0 + (tx << 2)) = v;
        }
    }
}

// ---------------- edge scatter-mean (masked) --------------------------------
// one warp per edge; lane handles 2 float4 chunks (8 floats, 8 atomics)
__global__ void scatter_kernel(const int* __restrict__ obj_idx,
                               const int* __restrict__ evt_idx, int nEdge)
{
    int gt   = blockIdx.x * blockDim.x + threadIdx.x;
    int e    = gt >> 5;
    int lane = gt & 31;
    if (e >= nEdge) return;
    int o = obj_idx[e];
    if (!g_mask[o]) return;                 // object never read -> skip
    int ev = evt_idx[e];
    const float4* src = (const float4*)(g_proj + (size_t)ev * OBJ_DIM);
    float* dst = g_sums + (size_t)o * OBJ_DIM;
    float4 v0 = src[lane];
    float4 v1 = src[lane + 32];
    int b0 = lane << 2, b1 = (lane + 32) << 2;
    atomicAdd(dst + b0 + 0, v0.x); atomicAdd(dst + b0 + 1, v0.y);
    atomicAdd(dst + b0 + 2, v0.z); atomicAdd(dst + b0 + 3, v0.w);
    atomicAdd(dst + b1 + 0, v1.x); atomicAdd(dst + b1 + 1, v1.y);
    atomicAdd(dst + b1 + 2, v1.z); atomicAdd(dst + b1 + 3, v1.w);
    if (lane == 0) atomicAdd(&g_cnt[o], 1.0f);
}

// sums -> profile (divide by max(cnt,1)), only for compacted rows
__global__ void divide_kernel() {
    int i = blockIdx.x * blockDim.x + threadIdx.x;
    int r = i >> 6;
    if (r >= g_count) return;
    int c = i & 63;
    int o = g_list[r];
    float scale = 1.f / fmaxf(g_cnt[o], 1.f);
    float4* p = (float4*)(g_sums + (size_t)o * OBJ_DIM);
    float4 v = p[c];
    v.x *= scale; v.y *= scale; v.z *= scale; v.w *= scale;
    p[c] = v;
}

// pass-through: out = object_X everywhere
__global__ void copy_kernel(const float* __restrict__ x, float* __restrict__ out,
                            int nObj) {
    int i = blockIdx.x * blockDim.x + threadIdx.x;
    if (i < nObj * 64) ((float4*)out)[i] = ((const float4*)x)[i];
}

__device__ __forceinline__ float sigm(float x) { return 1.f / (1.f + expf(-x)); }

// fused GRU gate epilogue + masked blend, overwrite only main rows
__global__ void gru_final_kernel(const float* __restrict__ objX,
                                 float* __restrict__ out, int nMain)
{
    int i = blockIdx.x * blockDim.x + threadIdx.x;
    int r = i >> 6;
    if (r >= g_count) return;
    int c = i & 63;
    int o = g_list[r];
    const float4* gi4 = (const float4*)(g_gi + (size_t)r * GRU3);
    const float4* gh4 = (const float4*)(g_gh + (size_t)r * GRU3);
    float4 ir = gi4[c],       hr = gh4[c];
    float4 iz = gi4[64 + c],  hz = gh4[64 + c];
    float4 in_ = gi4[128 + c], hn = gh4[128 + c];
    float4 h = ((const float4*)(objX + (size_t)o * OBJ_DIM))[c];

    float4 v;
    {
        float rg = sigm(ir.x + hr.x), z = sigm(iz.x + hz.x);
        float n = tanhf(in_.x + rg * hn.x);
        v.x = (1.f - z) * n + z * h.x;
    }
    {
        float rg = sigm(ir.y + hr.y), z = sigm(iz.y + hz.y);
        float n = tanhf(in_.y + rg * hn.y);
        v.y = (1.f - z) * n + z * h.y;
    }
    {
        float rg = sigm(ir.z + hr.z), z = sigm(iz.z + hz.z);
        float n = tanhf(in_.z + rg * hn.z);
        v.z = (1.f - z) * n + z * h.z;
    }
    {
        float rg = sigm(ir.w + hr.w), z = sigm(iz.w + hz.w);
        float n = tanhf(in_.w + rg * hn.w);
        v.w = (1.f - z) * n + z * h.w;
    }
    ((float4*)(out + (size_t)o * OBJ_DIM))[c] = v;
}

// ---------------- launch ----------------------------------------------------
extern "C" void kernel_launch(void* const* d_in, const int* in_sizes, int n_in,
                              void* d_out, int out_size)
{
    const float* object_X = (const float*)d_in[0];
    const float* event_X  = (const float*)d_in[1];
    const int*   lc_obj   = (const int*)d_in[2];
    const int*   lc_evt   = (const int*)d_in[3];
    const int*   main_idx = (const int*)d_in[4];
    const float* W_proj   = (const float*)d_in[5];
    const float* b_proj   = (const float*)d_in[6];
    const float* W_ih     = (const float*)d_in[7];
    const float* b_ih     = (const float*)d_in[8];
    const float* W_hh     = (const float*)d_in[9];
    const float* b_hh     = (const float*)d_in[10];
    float* out = (float*)d_out;

    int nObj  = in_sizes[0] / OBJ_DIM;
    int nEvt  = in_sizes[1] / OBJ_DIM;
    int nEdge = in_sizes[2];
    int nMain = in_sizes[4];

    float *p_proj, *p_sums, *p_gi, *p_gh;
    cudaGetSymbolAddress((void**)&p_proj, g_proj);
    cudaGetSymbolAddress((void**)&p_sums, g_sums);
    cudaGetSymbolAddress((void**)&p_gi,   g_gi);
    cudaGetSymbolAddress((void**)&p_gh,   g_gh);

    // 1. init scratch (sums, cnt, mask, count)
    zero_kernel<<<(nObj * 64 + 255) / 256, 256>>>(nObj);
    // 2. mask + compact unique main objects
    mask_kernel<<<(nMain + 255) / 256, 256>>>(main_idx, nMain);
    compact_kernel<<<(nObj + 255) / 256, 256>>>(nObj);
    // 3. per-event projection: proj = relu(event_X @ W_proj^T + b_proj)
    gemm_kernel<<<dim3(OBJ_DIM / BN, (nEvt + BM - 1) / BM), 256>>>(
        event_X, W_proj, b_proj, p_proj, nEvt, OBJ_DIM, OBJ_DIM,
        /*useList=*/0, /*useCount=*/0, /*relu=*/1);
    // 4. masked scatter-mean over edges
    scatter_kernel<<<(nEdge * 32 + 255) / 256, 256>>>(lc_obj, lc_evt, nEdge);
    divide_kernel<<<(nMain * 64 + 255) / 256, 256>>>();
    // 5. GRU input/hidden GEMMs on compacted rows only
    gemm_kernel<<<dim3(GRU3 / BN, (nMain + BM - 1) / BM), 256>>>(
        p_sums, W_ih, b_ih, p_gi, nMain, GRU3, OBJ_DIM, 1, 1, 0);
    gemm_kernel<<<dim3(GRU3 / BN, (nMain + BM - 1) / BM), 256>>>(
        object_X, W_hh, b_hh, p_gh, nMain, GRU3, OBJ_DIM, 1, 1, 0);
    // 6. pass-through copy + fused gate epilogue overwriting main rows
    copy_kernel<<<(nObj * 64 + 255) / 256, 256>>>(object_X, out, nObj);
    gru_final_kernel<<<(nMain * 64 + 255) / 256, 256>>>(object_X, out, nMain);
}

// round 9
// speedup vs baseline: 1.1757x; 1.1757x over previous
#include <cuda_runtime.h>
#include <math.h>

#define OBJ_DIM 256
#define GRU3    768
#define MAX_OBJ  50000
#define MAX_EVT  100000
#define MAX_EDGE 500000
#define MAX_MAIN 25000

// ---------------- device scratch (allocation-free per harness rules) --------
__device__ float g_proj[(size_t)MAX_EVT * OBJ_DIM];   // relu(event_X @ Wp^T + bp)
__device__ float g_sums[(size_t)MAX_OBJ * OBJ_DIM];   // scatter sums -> profile
__device__ float g_cnt[MAX_OBJ];
__device__ int   g_mask[MAX_OBJ];
__device__ int   g_list[MAX_MAIN];                    // compacted unique main objs
__device__ int   g_count;
__device__ float g_gi[(size_t)MAX_MAIN * GRU3];
__device__ float g_gh[(size_t)MAX_MAIN * GRU3];

// ---------------- small utility kernels -------------------------------------
__global__ void zero_kernel(int nObj) {
    int i = blockIdx.x * blockDim.x + threadIdx.x;
    if (i < nObj * 64) {
        ((float4*)g_sums)[i] = make_float4(0.f, 0.f, 0.f, 0.f);
    }
    if (i < nObj) { g_cnt[i] = 0.f; g_mask[i] = 0; }
    if (i == 0)   g_count = 0;
}

__global__ void mask_kernel(const int* __restrict__ main_idx, int nMain) {
    int i = blockIdx.x * blockDim.x + threadIdx.x;
    if (i < nMain) g_mask[main_idx[i]] = 1;
}

__global__ void compact_kernel(int nObj) {
    int i = blockIdx.x * blockDim.x + threadIdx.x;
    if (i < nObj && g_mask[i]) {
        int p = atomicAdd(&g_count, 1);
        g_list[p] = i;
    }
}

// ---------------- SGEMM: C[M,N] = act(A[M,K] @ W[N,K]^T + bias) -------------
// 128x128 block tile, BK=16, 256 threads, 8x8 per thread, double-buffered smem.
// useList: gather A rows through g_list; useCount: M = g_count (device-side).
#define BM 128
#define BN 128
#define BK 16

__global__ __launch_bounds__(256, 2) void gemm_kernel(
    const float* __restrict__ A, const float* __restrict__ W,
    const float* __restrict__ bias, float* __restrict__ C,
    int M, int N, int K, int useList, int useCount, int doRelu)
{
    int Meff = useCount ? g_count : M;
    int row0 = blockIdx.y * BM;
    if (row0 >= Meff) return;
    int n0 = blockIdx.x * BN;

    __shared__ __align__(16) float As[2][BK][BM + 4];
    __shared__ __align__(16) float Ws[2][BK][BN + 4];

    int t  = threadIdx.x;
    int tx = t & 15, ty = t >> 4;
    int mtop = ty << 2;            // 0..60
    int ntop = tx << 2;            // 0..60

    // loader mapping: 512 float4 per matrix per tile, 2 per thread.
    // idx -> row = idx>>2, kgrp = (idx&3)*4
    int li0 = t,       lr0 = li0 >> 2, lk0 = (li0 & 3) << 2;
    int li1 = t + 256, lr1 = li1 >> 2, lk1 = (li1 & 3) << 2;

    long arow0 = -1, arow1 = -1;
    {
        int gA0 = row0 + lr0, gA1 = row0 + lr1;
        if (gA0 < Meff) arow0 = useList ? (long)g_list[gA0] : (long)gA0;
        if (gA1 < Meff) arow1 = useList ? (long)g_list[gA1] : (long)gA1;
    }
    const float* wp0 = W + (size_t)(n0 + lr0) * K;
    const float* wp1 = W + (size_t)(n0 + lr1) * K;

    float acc[8][8];
#pragma unroll
    for (int i = 0; i < 8; i++)
#pragma unroll
        for (int j = 0; j < 8; j++) acc[i][j] = 0.f;

    float4 la0, la1, lw0, lw1;     // staged tile in registers

    auto loadTile = [&](int k0) {
        la0 = (arow0 >= 0) ? *(const float4*)(A + arow0 * (long)K + k0 + lk0)
                           : make_float4(0.f, 0.f, 0.f, 0.f);
        la1 = (arow1 >= 0) ? *(const float4*)(A + arow1 * (long)K + k0 + lk1)
                           : make_float4(0.f, 0.f, 0.f, 0.f);
        lw0 = *(const float4*)(wp0 + k0 + lk0);
        lw1 = *(const float4*)(wp1 + k0 + lk1);
    };
    auto storeTile = [&](int buf) {
        As[buf][lk0 + 0][lr0] = la0.x; As[buf][lk0 + 1][lr0] = la0.y;
        As[buf][lk0 + 2][lr0] = la0.z; As[buf][lk0 + 3][lr0] = la0.w;
        As[buf][lk1 + 0][lr1] = la1.x; As[buf][lk1 + 1][lr1] = la1.y;
        As[buf][lk1 + 2][lr1] = la1.z; As[buf][lk1 + 3][lr1] = la1.w;
        Ws[buf][lk0 + 0][lr0] = lw0.x; Ws[buf][lk0 + 1][lr0] = lw0.y;
        Ws[buf][lk0 + 2][lr0] = lw0.z; Ws[buf][lk0 + 3][lr0] = lw0.w;
        Ws[buf][lk1 + 0][lr1] = lw1.x; Ws[buf][lk1 + 1][lr1] = lw1.y;
        Ws[buf][lk1 + 2][lr1] = lw1.z; Ws[buf][lk1 + 3][lr1] = lw1.w;
    };

    int nT = K / BK;
    loadTile(0);
    storeTile(0);
    __syncthreads();
    int cur = 0;

    for (int kt = 0; kt < nT; kt++) {
        if (kt + 1 < nT) loadTile((kt + 1) * BK);

#pragma unroll
        for (int k = 0; k < BK; k++) {
            float4 av0 = *(const float4*)&As[cur][k][mtop];
            float4 av1 = *(const float4*)&As[cur][k][mtop + 64];
            float4 bv0 = *(const float4*)&Ws[cur][k][ntop];
            float4 bv1 = *(const float4*)&Ws[cur][k][ntop + 64];
            float am[8] = {av0.x, av0.y, av0.z, av0.w, av1.x, av1.y, av1.z, av1.w};
            float bn[8] = {bv0.x, bv0.y, bv0.z, bv0.w, bv1.x, bv1.y, bv1.z, bv1.w};
#pragma unroll
            for (int i = 0; i < 8; i++)
#pragma unroll
                for (int j = 0; j < 8; j++)
                    acc[i][j] += am[i] * bn[j];
        }

        if (kt + 1 < nT) storeTile(cur ^ 1);
        __syncthreads();
        cur ^= 1;
    }

    float4 bb0 = *(const float4*)(bias + n0 + ntop);
    float4 bb1 = *(const float4*)(bias + n0 + ntop + 64);
#pragma unroll
    for (int i = 0; i < 8; i++) {
        int m = row0 + ((i < 4) ? (mtop + i) : (mtop + 60 + i));  // +64+(i-4)
        if (m >= Meff) continue;
        float4 v0, v1;
        v0.x = acc[i][0] + bb0.x; v0.y = acc[i][1] + bb0.y;
        v0.z = acc[i][2] + bb0.z; v0.w = acc[i][3] + bb0.w;
        v1.x = acc[i][4] + bb1.x; v1.y = acc[i][5] + bb1.y;
        v1.z = acc[i][6] + bb1.z; v1.w = acc[i][7] + bb1.w;
        if (doRelu) {
            v0.x = fmaxf(v0.x, 0.f); v0.y = fmaxf(v0.y, 0.f);
            v0.z = fmaxf(v0.z, 0.f); v0.w = fmaxf(v0.w, 0.f);
            v1.x = fmaxf(v1.x, 0.f); v1.y = fmaxf(v1.y, 0.f);
            v1.z = fmaxf(v1.z, 0.f); v1.w = fmaxf(v1.w, 0.f);
        }
        *(float4*)(C + (size_t)m * N + n0 + ntop)      = v0;
        *(float4*)(C + (size_t)m * N + n0 + ntop + 64) = v1;
    }
}

// ---------------- edge scatter-mean (masked) --------------------------------
// one warp per edge; lane handles 2 float4 chunks (8 floats, 8 atomics)
__global__ void scatter_kernel(const int* __restrict__ obj_idx,
                               const int* __restrict__ evt_idx, int nEdge)
{
    int gt   = blockIdx.x * blockDim.x + threadIdx.x;
    int e    = gt >> 5;
    int lane = gt & 31;
    if (e >= nEdge) return;
    int o = obj_idx[e];
    if (!g_mask[o]) return;                 // object never read -> skip
    int ev = evt_idx[e];
    const float4* src = (const float4*)(g_proj + (size_t)ev * OBJ_DIM);
    float* dst = g_sums + (size_t)o * OBJ_DIM;
    float4 v0 = src[lane];
    float4 v1 = src[lane + 32];
    int b0 = lane << 2, b1 = (lane + 32) << 2;
    atomicAdd(dst + b0 + 0, v0.x); atomicAdd(dst + b0 + 1, v0.y);
    atomicAdd(dst + b0 + 2, v0.z); atomicAdd(dst + b0 + 3, v0.w);
    atomicAdd(dst + b1 + 0, v1.x); atomicAdd(dst + b1 + 1, v1.y);
    atomicAdd(dst + b1 + 2, v1.z); atomicAdd(dst + b1 + 3, v1.w);
    if (lane == 0) atomicAdd(&g_cnt[o], 1.0f);
}

// sums -> profile (divide by max(cnt,1)), only for compacted rows
__global__ void divide_kernel() {
    int i = blockIdx.x * blockDim.x + threadIdx.x;
    int r = i >> 6;
    if (r >= g_count) return;
    int c = i & 63;
    int o = g_list[r];
    float scale = 1.f / fmaxf(g_cnt[o], 1.f);
    float4* p = (float4*)(g_sums + (size_t)o * OBJ_DIM);
    float4 v = p[c];
    v.x *= scale; v.y *= scale; v.z *= scale; v.w *= scale;
    p[c] = v;
}

// pass-through: out = object_X everywhere
__global__ void copy_kernel(const float* __restrict__ x, float* __restrict__ out,
                            int nObj) {
    int i = blockIdx.x * blockDim.x + threadIdx.x;
    if (i < nObj * 64) ((float4*)out)[i] = ((const float4*)x)[i];
}

__device__ __forceinline__ float sigm(float x) { return 1.f / (1.f + expf(-x)); }

// fused GRU gate epilogue + masked blend, overwrite only main rows
__global__ void gru_final_kernel(const float* __restrict__ objX,
                                 float* __restrict__ out, int nMain)
{
    int i = blockIdx.x * blockDim.x + threadIdx.x;
    int r = i >> 6;
    if (r >= g_count) return;
    int c = i & 63;
    int o = g_list[r];
    const float4* gi4 = (const float4*)(g_gi + (size_t)r * GRU3);
    const float4* gh4 = (const float4*)(g_gh + (size_t)r * GRU3);
    float4 ir = gi4[c],       hr = gh4[c];
    float4 iz = gi4[64 + c],  hz = gh4[64 + c];
    float4 in_ = gi4[128 + c], hn = gh4[128 + c];
    float4 h = ((const float4*)(objX + (size_t)o * OBJ_DIM))[c];

    float4 v;
    {
        float rg = sigm(ir.x + hr.x), z = sigm(iz.x + hz.x);
        float n = tanhf(in_.x + rg * hn.x);
        v.x = (1.f - z) * n + z * h.x;
    }
    {
        float rg = sigm(ir.y + hr.y), z = sigm(iz.y + hz.y);
        float n = tanhf(in_.y + rg * hn.y);
        v.y = (1.f - z) * n + z * h.y;
    }
    {
        float rg = sigm(ir.z + hr.z), z = sigm(iz.z + hz.z);
        float n = tanhf(in_.z + rg * hn.z);
        v.z = (1.f - z) * n + z * h.z;
    }
    {
        float rg = sigm(ir.w + hr.w), z = sigm(iz.w + hz.w);
        float n = tanhf(in_.w + rg * hn.w);
        v.w = (1.f - z) * n + z * h.w;
    }
    ((float4*)(out + (size_t)o * OBJ_DIM))[c] = v;
}

// ---------------- launch ----------------------------------------------------
extern "C" void kernel_launch(void* const* d_in, const int* in_sizes, int n_in,
                              void* d_out, int out_size)
{
    const float* object_X = (const float*)d_in[0];
    const float* event_X  = (const float*)d_in[1];
    const int*   lc_obj   = (const int*)d_in[2];
    const int*   lc_evt   = (const int*)d_in[3];
    const int*   main_idx = (const int*)d_in[4];
    const float* W_proj   = (const float*)d_in[5];
    const float* b_proj   = (const float*)d_in[6];
    const float* W_ih     = (const float*)d_in[7];
    const float* b_ih     = (const float*)d_in[8];
    const float* W_hh     = (const float*)d_in[9];
    const float* b_hh     = (const float*)d_in[10];
    float* out = (float*)d_out;

    int nObj  = in_sizes[0] / OBJ_DIM;
    int nEvt  = in_sizes[1] / OBJ_DIM;
    int nEdge = in_sizes[2];
    int nMain = in_sizes[4];

    float *p_proj, *p_sums, *p_gi, *p_gh;
    cudaGetSymbolAddress((void**)&p_proj, g_proj);
    cudaGetSymbolAddress((void**)&p_sums, g_sums);
    cudaGetSymbolAddress((void**)&p_gi,   g_gi);
    cudaGetSymbolAddress((void**)&p_gh,   g_gh);

    // 1. init scratch (sums, cnt, mask, count)
    zero_kernel<<<(nObj * 64 + 255) / 256, 256>>>(nObj);
    // 2. mask + compact unique main objects
    mask_kernel<<<(nMain + 255) / 256, 256>>>(main_idx, nMain);
    compact_kernel<<<(nObj + 255) / 256, 256>>>(nObj);
    // 3. per-event projection: proj = relu(event_X @ W_proj^T + b_proj)
    gemm_kernel<<<dim3(OBJ_DIM / BN, (nEvt + BM - 1) / BM), 256>>>(
        event_X, W_proj, b_proj, p_proj, nEvt, OBJ_DIM, OBJ_DIM,
        /*useList=*/0, /*useCount=*/0, /*relu=*/1);
    // 4. masked scatter-mean over edges
    scatter_kernel<<<(nEdge * 32 + 255) / 256, 256>>>(lc_obj, lc_evt, nEdge);
    divide_kernel<<<(nMain * 64 + 255) / 256, 256>>>();
    // 5. GRU input/hidden GEMMs on compacted rows only
    gemm_kernel<<<dim3(GRU3 / BN, (nMain + BM - 1) / BM), 256>>>(
        p_sums, W_ih, b_ih, p_gi, nMain, GRU3, OBJ_DIM, 1, 1, 0);
    gemm_kernel<<<dim3(GRU3 / BN, (nMain + BM - 1) / BM), 256>>>(
        object_X, W_hh, b_hh, p_gh, nMain, GRU3, OBJ_DIM, 1, 1, 0);
    // 6. pass-through copy + fused gate epilogue overwriting main rows
    copy_kernel<<<(nObj * 64 + 255) / 256, 256>>>(object_X, out, nObj);
    gru_final_kernel<<<(nMain * 64 + 255) / 256, 256>>>(object_X, out, nMain);
}

// round 13
// speedup vs baseline: 1.5213x; 1.2939x over previous
#include <cuda_runtime.h>
#include <cuda_bf16.h>
#include <mma.h>
#include <math.h>
#include <stdint.h>

using namespace nvcuda;

#define OBJ_DIM 256
#define GRU3    768
#define MAX_OBJ  50000
#define MAX_EVT  100000
#define MAX_EDGE 500000
#define MAX_MAIN 25000

// ---------------- device scratch (allocation-free per harness rules) --------
__device__ float g_proj[(size_t)MAX_EVT * OBJ_DIM];   // relu(event_X @ Wp^T + bp)
__device__ float g_sums[(size_t)MAX_OBJ * OBJ_DIM];   // scatter sums -> profile
__device__ float g_cnt[MAX_OBJ];
__device__ int   g_mask[MAX_OBJ];
__device__ int   g_list[MAX_MAIN];                    // compacted unique main objs
__device__ int   g_count;
__device__ float g_gi[(size_t)MAX_MAIN * GRU3];
__device__ float g_gh[(size_t)MAX_MAIN * GRU3];

// fp32 -> (bf16 hi, bf16 lo) packed pairs (lo = residual, 16 effective bits)
__device__ __forceinline__ void split2(float a, float b, uint32_t& h, uint32_t& l) {
    __nv_bfloat16 ha = __float2bfloat16(a), hb = __float2bfloat16(b);
    float la = a - __bfloat162float(ha);
    float lb = b - __bfloat162float(hb);
    h = (uint32_t)__bfloat16_as_ushort(ha) | ((uint32_t)__bfloat16_as_ushort(hb) << 16);
    __nv_bfloat162 lp = __floats2bfloat162_rn(la, lb);
    l = *reinterpret_cast<uint32_t*>(&lp);
}

// ---------------- WMMA bf16x3 GEMM: C[M,N] = act(A[M,256] @ W[N,256]^T + b) -
// Block 128x128, BK=32, 8 warps (4m x 2n), warp tile 32x64 (2x4 wmma 16x16x16).
// bf16 split: acc += Ah*Bh + Ah*Bl + Al*Bh  (fp32 accumulate).
// useList: gather A rows through g_list; useCount: M = g_count (device-side).
#define LDA 40                    /* bf16 tile leading dim (80 B, 16B-mult) */
#define TILE_E (128 * LDA)        /* 5120 elems per tile */
#define BUF_E  (4 * TILE_E)       /* Ah, Al, Bh, Bl */
#define LDE 72                    /* epilogue f32 ldm */
#define GEMM_SMEM 81920           /* 2 x 40960 B buffers (epilogue 73728 fits) */

__global__ __launch_bounds__(256, 1) void gemm_wmma(
    const float* __restrict__ A, const float* __restrict__ W,
    const float* __restrict__ bias, float* __restrict__ C,
    int M, int N, int K, int useList, int useCount, int doRelu)
{
    extern __shared__ __align__(128) float smemf[];
    __nv_bfloat16* sB = (__nv_bfloat16*)smemf;

    int Meff = useCount ? g_count : M;
    int row0 = blockIdx.y * 128;
    if (row0 >= Meff) return;
    int n0 = blockIdx.x * 128;

    int t = threadIdx.x;
    int wid = t >> 5;
    int warp_m = wid >> 1, warp_n = wid & 1;

    // loader mapping: thread t handles rows lr, lr+64; cols lcolg..lcolg+7
    int lr = t >> 2;
    int lcolg = (t & 3) << 3;
    long arow0 = -1, arow1 = -1;
    {
        int g0 = row0 + lr, g1 = row0 + lr + 64;
        if (g0 < Meff) arow0 = useList ? (long)g_list[g0] : (long)g0;
        if (g1 < Meff) arow1 = useList ? (long)g_list[g1] : (long)g1;
    }
    const float* wp0 = W + (size_t)(n0 + lr) * K;
    const float* wp1 = W + (size_t)(n0 + lr + 64) * K;

    wmma::fragment<wmma::accumulator, 16, 16, 16, float> acc[2][4];
#pragma unroll
    for (int i = 0; i < 2; i++)
#pragma unroll
        for (int j = 0; j < 4; j++) wmma::fill_fragment(acc[i][j], 0.0f);

    float4 a0x, a0y, a1x, a1y, w0x, w0y, w1x, w1y;   // staged k-tile

    auto loadS = [&](int k0) {
        float4 z = make_float4(0.f, 0.f, 0.f, 0.f);
        if (arow0 >= 0) {
            const float* p = A + arow0 * (long)K + k0 + lcolg;
            a0x = *(const float4*)p; a0y = *(const float4*)(p + 4);
        } else { a0x = z; a0y = z; }
        if (arow1 >= 0) {
            const float* p = A + arow1 * (long)K + k0 + lcolg;
            a1x = *(const float4*)p; a1y = *(const float4*)(p + 4);
        } else { a1x = z; a1y = z; }
        w0x = *(const float4*)(wp0 + k0 + lcolg);
        w0y = *(const float4*)(wp0 + k0 + lcolg + 4);
        w1x = *(const float4*)(wp1 + k0 + lcolg);
        w1y = *(const float4*)(wp1 + k0 + lcolg + 4);
    };
    auto storeS = [&](int buf) {
        __nv_bfloat16* base = sB + buf * BUF_E;
        int off0 = lr * LDA + lcolg;
        int off1 = (lr + 64) * LDA + lcolg;
        uint32_t h[4], l[4];
        split2(a0x.x, a0x.y, h[0], l[0]); split2(a0x.z, a0x.w, h[1], l[1]);
        split2(a0y.x, a0y.y, h[2], l[2]); split2(a0y.z, a0y.w, h[3], l[3]);
        *(uint4*)(base + off0)          = make_uint4(h[0], h[1], h[2], h[3]);
        *(uint4*)(base + TILE_E + off0) = make_uint4(l[0], l[1], l[2], l[3]);
        split2(a1x.x, a1x.y, h[0], l[0]); split2(a1x.z, a1x.w, h[1], l[1]);
        split2(a1y.x, a1y.y, h[2], l[2]); split2(a1y.z, a1y.w, h[3], l[3]);
        *(uint4*)(base + off1)          = make_uint4(h[0], h[1], h[2], h[3]);
        *(uint4*)(base + TILE_E + off1) = make_uint4(l[0], l[1], l[2], l[3]);
        split2(w0x.x, w0x.y, h[0], l[0]); split2(w0x.z, w0x.w, h[1], l[1]);
        split2(w0y.x, w0y.y, h[2], l[2]); split2(w0y.z, w0y.w, h[3], l[3]);
        *(uint4*)(base + 2 * TILE_E + off0) = make_uint4(h[0], h[1], h[2], h[3]);
        *(uint4*)(base + 3 * TILE_E + off0) = make_uint4(l[0], l[1], l[2], l[3]);
        split2(w1x.x, w1x.y, h[0], l[0]); split2(w1x.z, w1x.w, h[1], l[1]);
        split2(w1y.x, w1y.y, h[2], l[2]); split2(w1y.z, w1y.w, h[3], l[3]);
        *(uint4*)(base + 2 * TILE_E + off1) = make_uint4(h[0], h[1], h[2], h[3]);
        *(uint4*)(base + 3 * TILE_E + off1) = make_uint4(l[0], l[1], l[2], l[3]);
    };
    auto compute = [&](int buf) {
        const __nv_bfloat16* Ah = sB + buf * BUF_E;
        const __nv_bfloat16* Al = Ah + TILE_E;
        const __nv_bfloat16* Bh = Ah + 2 * TILE_E;
        const __nv_bfloat16* Bl = Ah + 3 * TILE_E;
#pragma unroll
        for (int kk = 0; kk < 32; kk += 16) {
            wmma::fragment<wmma::matrix_a, 16, 16, 16, __nv_bfloat16,
                           wmma::row_major> ah[2], al[2];
#pragma unroll
            for (int i = 0; i < 2; i++) {
                int r = (warp_m * 32 + i * 16) * LDA + kk;
                wmma::load_matrix_sync(ah[i], Ah + r, LDA);
                wmma::load_matrix_sync(al[i], Al + r, LDA);
            }
#pragma unroll
            for (int j = 0; j < 4; j++) {
                wmma::fragment<wmma::matrix_b, 16, 16, 16, __nv_bfloat16,
                               wmma::col_major> bh, bl;
                int rb = (warp_n * 64 + j * 16) * LDA + kk;
                wmma::load_matrix_sync(bh, Bh + rb, LDA);
                wmma::load_matrix_sync(bl, Bl + rb, LDA);
#pragma unroll
                for (int i = 0; i < 2; i++) {
                    wmma::mma_sync(acc[i][j], ah[i], bh, acc[i][j]);
                    wmma::mma_sync(acc[i][j], ah[i], bl, acc[i][j]);
                    wmma::mma_sync(acc[i][j], al[i], bh, acc[i][j]);
                }
            }
        }
    };

    int nT = K / 32;              // 8
    loadS(0);
    storeS(0);
    __syncthreads();
    int cur = 0;
    for (int kt = 0; kt < nT; kt++) {
        if (kt + 1 < nT) loadS((kt + 1) * 32);
        compute(cur);
        if (kt + 1 < nT) storeS(cur ^ 1);
        __syncthreads();
        cur ^= 1;
    }

    // epilogue: acc frags -> smem (f32) -> bias/relu -> C
    __syncthreads();
    float* ep = smemf + wid * (32 * LDE);
#pragma unroll
    for (int i = 0; i < 2; i++)
#pragma unroll
        for (int j = 0; j < 4; j++)
            wmma::store_matrix_sync(ep + i * 16 * LDE + j * 16, acc[i][j],
                                    LDE, wmma::mem_row_major);
    __syncthreads();
#pragma unroll
    for (int it = 0; it < 16; it++) {
        int idx = t + it * 256;           // 0..4095
        int row = idx >> 5;               // 0..127
        int col = (idx & 31) << 2;        // 0..124
        int m = row0 + row;
        if (m >= Meff) continue;
        int w = ((row >> 5) << 1) | (col >> 6);
        const float* src = smemf + w * (32 * LDE) + (row & 31) * LDE + (col & 63);
        float4 v = *(const float4*)src;
        float4 bb = *(const float4*)(bias + n0 + col);
        v.x += bb.x; v.y += bb.y; v.z += bb.z; v.w += bb.w;
        if (doRelu) {
            v.x = fmaxf(v.x, 0.f); v.y = fmaxf(v.y, 0.f);
            v.z = fmaxf(v.z, 0.f); v.w = fmaxf(v.w, 0.f);
        }
        *(float4*)(C + (size_t)m * N + n0 + col) = v;
    }
}

// ---------------- small utility kernels -------------------------------------
__global__ void zero_kernel(int nObj) {
    int i = blockIdx.x * blockDim.x + threadIdx.x;
    if (i < nObj * 64) {
        ((float4*)g_sums)[i] = make_float4(0.f, 0.f, 0.f, 0.f);
    }
    if (i < nObj) { g_cnt[i] = 0.f; g_mask[i] = 0; }
    if (i == 0)   g_count = 0;
}

__global__ void mask_kernel(const int* __restrict__ main_idx, int nMain) {
    int i = blockIdx.x * blockDim.x + threadIdx.x;
    if (i < nMain) g_mask[main_idx[i]] = 1;
}

__global__ void compact_kernel(int nObj) {
    int i = blockIdx.x * blockDim.x + threadIdx.x;
    if (i < nObj && g_mask[i]) {
        int p = atomicAdd(&g_count, 1);
        g_list[p] = i;
    }
}

// edge scatter-mean (masked): one warp per edge
__global__ void scatter_kernel(const int* __restrict__ obj_idx,
                               const int* __restrict__ evt_idx, int nEdge)
{
    int gt   = blockIdx.x * blockDim.x + threadIdx.x;
    int e    = gt >> 5;
    int lane = gt & 31;
    if (e >= nEdge) return;
    int o = obj_idx[e];
    if (!g_mask[o]) return;
    int ev = evt_idx[e];
    const float4* src = (const float4*)(g_proj + (size_t)ev * OBJ_DIM);
    float* dst = g_sums + (size_t)o * OBJ_DIM;
    float4 v0 = src[lane];
    float4 v1 = src[lane + 32];
    int b0 = lane << 2, b1 = (lane + 32) << 2;
    atomicAdd(dst + b0 + 0, v0.x); atomicAdd(dst + b0 + 1, v0.y);
    atomicAdd(dst + b0 + 2, v0.z); atomicAdd(dst + b0 + 3, v0.w);
    atomicAdd(dst + b1 + 0, v1.x); atomicAdd(dst + b1 + 1, v1.y);
    atomicAdd(dst + b1 + 2, v1.z); atomicAdd(dst + b1 + 3, v1.w);
    if (lane == 0) atomicAdd(&g_cnt[o], 1.0f);
}

__global__ void divide_kernel() {
    int i = blockIdx.x * blockDim.x + threadIdx.x;
    int r = i >> 6;
    if (r >= g_count) return;
    int c = i & 63;
    int o = g_list[r];
    float scale = 1.f / fmaxf(g_cnt[o], 1.f);
    float4* p = (float4*)(g_sums + (size_t)o * OBJ_DIM);
    float4 v = p[c];
    v.x *= scale; v.y *= scale; v.z *= scale; v.w *= scale;
    p[c] = v;
}

__global__ void copy_kernel(const float* __restrict__ x, float* __restrict__ out,
                            int nObj) {
    int i = blockIdx.x * blockDim.x + threadIdx.x;
    if (i < nObj * 64) ((float4*)out)[i] = ((const float4*)x)[i];
}

__device__ __forceinline__ float sigm(float x) { return 1.f / (1.f + expf(-x)); }

__global__ void gru_final_kernel(const float* __restrict__ objX,
                                 float* __restrict__ out, int nMain)
{
    int i = blockIdx.x * blockDim.x + threadIdx.x;
    int r = i >> 6;
    if (r >= g_count) return;
    int c = i & 63;
    int o = g_list[r];
    const float4* gi4 = (const float4*)(g_gi + (size_t)r * GRU3);
    const float4* gh4 = (const float4*)(g_gh + (size_t)r * GRU3);
    float4 ir = gi4[c],        hr = gh4[c];
    float4 iz = gi4[64 + c],   hz = gh4[64 + c];
    float4 in_ = gi4[128 + c], hn = gh4[128 + c];
    float4 h = ((const float4*)(objX + (size_t)o * OBJ_DIM))[c];

    float4 v;
    { float rg = sigm(ir.x + hr.x), z = sigm(iz.x + hz.x);
      float n = tanhf(in_.x + rg * hn.x); v.x = (1.f - z) * n + z * h.x; }
    { float rg = sigm(ir.y + hr.y), z = sigm(iz.y + hz.y);
      float n = tanhf(in_.y + rg * hn.y); v.y = (1.f - z) * n + z * h.y; }
    { float rg = sigm(ir.z + hr.z), z = sigm(iz.z + hz.z);
      float n = tanhf(in_.z + rg * hn.z); v.z = (1.f - z) * n + z * h.z; }
    { float rg = sigm(ir.w + hr.w), z = sigm(iz.w + hz.w);
      float n = tanhf(in_.w + rg * hn.w); v.w = (1.f - z) * n + z * h.w; }
    ((float4*)(out + (size_t)o * OBJ_DIM))[c] = v;
}

// ---------------- launch ----------------------------------------------------
extern "C" void kernel_launch(void* const* d_in, const int* in_sizes, int n_in,
                              void* d_out, int out_size)
{
    const float* object_X = (const float*)d_in[0];
    const float* event_X  = (const float*)d_in[1];
    const int*   lc_obj   = (const int*)d_in[2];
    const int*   lc_evt   = (const int*)d_in[3];
    const int*   main_idx = (const int*)d_in[4];
    const float* W_proj   = (const float*)d_in[5];
    const float* b_proj   = (const float*)d_in[6];
    const float* W_ih     = (const float*)d_in[7];
    const float* b_ih     = (const float*)d_in[8];
    const float* W_hh     = (const float*)d_in[9];
    const float* b_hh     = (const float*)d_in[10];
    float* out = (float*)d_out;

    int nObj  = in_sizes[0] / OBJ_DIM;
    int nEvt  = in_sizes[1] / OBJ_DIM;
    int nEdge = in_sizes[2];
    int nMain = in_sizes[4];

    float *p_proj, *p_sums, *p_gi, *p_gh;
    cudaGetSymbolAddress((void**)&p_proj, g_proj);
    cudaGetSymbolAddress((void**)&p_sums, g_sums);
    cudaGetSymbolAddress((void**)&p_gi,   g_gi);
    cudaGetSymbolAddress((void**)&p_gh,   g_gh);

    cudaFuncSetAttribute(gemm_wmma, cudaFuncAttributeMaxDynamicSharedMemorySize,
                         GEMM_SMEM);

    // 1. init scratch (sums, cnt, mask, count)
    zero_kernel<<<(nObj * 64 + 255) / 256, 256>>>(nObj);
    // 2. mask + compact unique main objects
    mask_kernel<<<(nMain + 255) / 256, 256>>>(main_idx, nMain);
    compact_kernel<<<(nObj + 255) / 256, 256>>>(nObj);
    // 3. per-event projection: proj = relu(event_X @ W_proj^T + b_proj)
    gemm_wmma<<<dim3(2, (nEvt + 127) / 128), 256, GEMM_SMEM>>>(
        event_X, W_proj, b_proj, p_proj, nEvt, OBJ_DIM, OBJ_DIM, 0, 0, 1);
    // 4. masked scatter-mean over edges
    scatter_kernel<<<(nEdge * 32 + 255) / 256, 256>>>(lc_obj, lc_evt, nEdge);
    divide_kernel<<<(nMain * 64 + 255) / 256, 256>>>();
    // 5. GRU input/hidden GEMMs on compacted rows only
    gemm_wmma<<<dim3(6, (nMain + 127) / 128), 256, GEMM_SMEM>>>(
        p_sums, W_ih, b_ih, p_gi, nMain, GRU3, OBJ_DIM, 1, 1, 0);
    gemm_wmma<<<dim3(6, (nMain + 127) / 128), 256, GEMM_SMEM>>>(
        object_X, W_hh, b_hh, p_gh, nMain, GRU3, OBJ_DIM, 1, 1, 0);
    // 6. pass-through copy + fused gate epilogue overwriting main rows
    copy_kernel<<<(nObj * 64 + 255) / 256, 256>>>(object_X, out, nObj);
    gru_final_kernel<<<(nMain * 64 + 255) / 256, 256>>>(object_X, out, nMain);
}

// round 14
// speedup vs baseline: 1.5444x; 1.0151x over previous
#include <cuda_runtime.h>
#include <cuda_bf16.h>
#include <mma.h>
#include <math.h>
#include <stdint.h>

using namespace nvcuda;

#define OBJ_DIM 256
#define GRU3    768
#define MAX_OBJ  50000
#define MAX_EVT  100000
#define MAX_EDGE 500000
#define MAX_MAIN 25000

// ---------------- device scratch (allocation-free per harness rules) --------
__device__ float g_proj[(size_t)MAX_EVT * OBJ_DIM];   // relu(event_X @ Wp^T + bp)
__device__ float g_sums[(size_t)MAX_OBJ * OBJ_DIM];   // scatter sums -> profile
__device__ float g_cnt[MAX_OBJ];
__device__ int   g_mask[MAX_OBJ];
__device__ int   g_list[MAX_MAIN];                    // compacted unique main objs
__device__ int   g_count;
__device__ float g_gi[(size_t)MAX_MAIN * GRU3];
__device__ float g_gh[(size_t)MAX_MAIN * GRU3];

// fp32 -> (bf16 hi, bf16 lo) packed pairs (lo = residual, 16 effective bits)
__device__ __forceinline__ void split2(float a, float b, uint32_t& h, uint32_t& l) {
    __nv_bfloat16 ha = __float2bfloat16(a), hb = __float2bfloat16(b);
    float la = a - __bfloat162float(ha);
    float lb = b - __bfloat162float(hb);
    h = (uint32_t)__bfloat16_as_ushort(ha) | ((uint32_t)__bfloat16_as_ushort(hb) << 16);
    __nv_bfloat162 lp = __floats2bfloat162_rn(la, lb);
    l = *reinterpret_cast<uint32_t*>(&lp);
}

// ---------------- WMMA bf16x3 GEMM: C[M,N] = act(A[M,256] @ W[N,256]^T + b) -
// Block 128x128, BK=32, 16 warps (4m x 4n), warp tile 32x32 (2x2 wmma 16x16x16).
// bf16 split: acc += Ah*Bh + Ah*Bl + Al*Bh  (fp32 accumulate).
// useList: gather A rows through g_list; useCount: M = g_count (device-side).
#define LDA 40                    /* bf16 tile leading dim (80 B, 16B-mult) */
#define TILE_E (128 * LDA)        /* 5120 bf16 per half-tile */
#define BUF_E  (4 * TILE_E)       /* Ah, Al, Bh, Bl */
#define LDE 132                   /* epilogue f32 ldm */
#define GEMM_SMEM 81920           /* 2 x 40960 B buffers; epilogue 67584 fits */

__global__ __launch_bounds__(512, 1) void gemm_wmma(
    const float* __restrict__ A, const float* __restrict__ W,
    const float* __restrict__ bias, float* __restrict__ C,
    int M, int N, int K, int useList, int useCount, int doRelu)
{
    extern __shared__ __align__(128) float smemf[];
    __nv_bfloat16* sB = (__nv_bfloat16*)smemf;

    int Meff = useCount ? g_count : M;
    int row0 = blockIdx.y * 128;
    if (row0 >= Meff) return;
    int n0 = blockIdx.x * 128;

    int t = threadIdx.x;
    int wid = t >> 5;
    int warp_m = wid >> 2, warp_n = wid & 3;

    // loader mapping: thread t handles row lr (one A row, one W row), 8 cols
    int lr = t >> 2;
    int lcolg = (t & 3) << 3;
    long arow = -1;
    {
        int g0 = row0 + lr;
        if (g0 < Meff) arow = useList ? (long)g_list[g0] : (long)g0;
    }
    const float* wp = W + (size_t)(n0 + lr) * K;

    wmma::fragment<wmma::accumulator, 16, 16, 16, float> acc[2][2];
#pragma unroll
    for (int i = 0; i < 2; i++)
#pragma unroll
        for (int j = 0; j < 2; j++) wmma::fill_fragment(acc[i][j], 0.0f);

    float4 ax, ay, wx, wy;        // staged k-tile (16 floats)

    auto loadS = [&](int k0) {
        float4 z = make_float4(0.f, 0.f, 0.f, 0.f);
        if (arow >= 0) {
            const float* p = A + arow * (long)K + k0 + lcolg;
            ax = *(const float4*)p; ay = *(const float4*)(p + 4);
        } else { ax = z; ay = z; }
        wx = *(const float4*)(wp + k0 + lcolg);
        wy = *(const float4*)(wp + k0 + lcolg + 4);
    };
    auto storeS = [&](int buf) {
        __nv_bfloat16* base = sB + buf * BUF_E;
        int off = lr * LDA + lcolg;
        uint32_t h[4], l[4];
        split2(ax.x, ax.y, h[0], l[0]); split2(ax.z, ax.w, h[1], l[1]);
        split2(ay.x, ay.y, h[2], l[2]); split2(ay.z, ay.w, h[3], l[3]);
        *(uint4*)(base + off)          = make_uint4(h[0], h[1], h[2], h[3]);
        *(uint4*)(base + TILE_E + off) = make_uint4(l[0], l[1], l[2], l[3]);
        split2(wx.x, wx.y, h[0], l[0]); split2(wx.z, wx.w, h[1], l[1]);
        split2(wy.x, wy.y, h[2], l[2]); split2(wy.z, wy.w, h[3], l[3]);
        *(uint4*)(base + 2 * TILE_E + off) = make_uint4(h[0], h[1], h[2], h[3]);
        *(uint4*)(base + 3 * TILE_E + off) = make_uint4(l[0], l[1], l[2], l[3]);
    };
    auto compute = [&](int buf) {
        const __nv_bfloat16* Ah = sB + buf * BUF_E;
        const __nv_bfloat16* Al = Ah + TILE_E;
        const __nv_bfloat16* Bh = Ah + 2 * TILE_E;
        const __nv_bfloat16* Bl = Ah + 3 * TILE_E;
#pragma unroll
        for (int kk = 0; kk < 32; kk += 16) {
            wmma::fragment<wmma::matrix_a, 16, 16, 16, __nv_bfloat16,
                           wmma::row_major> ah[2], al[2];
#pragma unroll
            for (int i = 0; i < 2; i++) {
                int r = (warp_m * 32 + i * 16) * LDA + kk;
                wmma::load_matrix_sync(ah[i], Ah + r, LDA);
                wmma::load_matrix_sync(al[i], Al + r, LDA);
            }
#pragma unroll
            for (int j = 0; j < 2; j++) {
                wmma::fragment<wmma::matrix_b, 16, 16, 16, __nv_bfloat16,
                               wmma::col_major> bh, bl;
                int rb = (warp_n * 32 + j * 16) * LDA + kk;
                wmma::load_matrix_sync(bh, Bh + rb, LDA);
                wmma::load_matrix_sync(bl, Bl + rb, LDA);
#pragma unroll
                for (int i = 0; i < 2; i++) {
                    wmma::mma_sync(acc[i][j], ah[i], bh, acc[i][j]);
                    wmma::mma_sync(acc[i][j], ah[i], bl, acc[i][j]);
                    wmma::mma_sync(acc[i][j], al[i], bh, acc[i][j]);
                }
            }
        }
    };

    int nT = K / 32;              // 8
    loadS(0);
    storeS(0);
    __syncthreads();
    int cur = 0;
    for (int kt = 0; kt < nT; kt++) {
        if (kt + 1 < nT) loadS((kt + 1) * 32);
        compute(cur);
        if (kt + 1 < nT) storeS(cur ^ 1);
        __syncthreads();
        cur ^= 1;
    }

    // epilogue: acc frags -> smem (f32, [128][LDE]) -> bias/relu -> C
    __syncthreads();
#pragma unroll
    for (int i = 0; i < 2; i++)
#pragma unroll
        for (int j = 0; j < 2; j++)
            wmma::store_matrix_sync(
                smemf + (size_t)(warp_m * 32 + i * 16) * LDE + warp_n * 32 + j * 16,
                acc[i][j], LDE, wmma::mem_row_major);
    __syncthreads();
#pragma unroll
    for (int it = 0; it < 8; it++) {
        int idx = t + it * 512;           // 0..4095
        int row = idx >> 5;               // 0..127
        int col = (idx & 31) << 2;        // 0..124
        int m = row0 + row;
        if (m >= Meff) continue;
        const float* src = smemf + (size_t)row * LDE + col;
        float4 v = *(const float4*)src;
        float4 bb = *(const float4*)(bias + n0 + col);
        v.x += bb.x; v.y += bb.y; v.z += bb.z; v.w += bb.w;
        if (doRelu) {
            v.x = fmaxf(v.x, 0.f); v.y = fmaxf(v.y, 0.f);
            v.z = fmaxf(v.z, 0.f); v.w = fmaxf(v.w, 0.f);
        }
        *(float4*)(C + (size_t)m * N + n0 + col) = v;
    }
}

// ---------------- small utility kernels -------------------------------------
__global__ void zero_kernel(int nObj) {
    int i = blockIdx.x * blockDim.x + threadIdx.x;
    if (i < nObj * 64) {
        ((float4*)g_sums)[i] = make_float4(0.f, 0.f, 0.f, 0.f);
    }
    if (i < nObj) { g_cnt[i] = 0.f; g_mask[i] = 0; }
    if (i == 0)   g_count = 0;
}

__global__ void mask_kernel(const int* __restrict__ main_idx, int nMain) {
    int i = blockIdx.x * blockDim.x + threadIdx.x;
    if (i < nMain) g_mask[main_idx[i]] = 1;
}

__global__ void compact_kernel(int nObj) {
    int i = blockIdx.x * blockDim.x + threadIdx.x;
    if (i < nObj && g_mask[i]) {
        int p = atomicAdd(&g_count, 1);
        g_list[p] = i;
    }
}

// edge scatter-mean (masked): one warp per edge
__global__ void scatter_kernel(const int* __restrict__ obj_idx,
                               const int* __restrict__ evt_idx, int nEdge)
{
    int gt   = blockIdx.x * blockDim.x + threadIdx.x;
    int e    = gt >> 5;
    int lane = gt & 31;
    if (e >= nEdge) return;
    int o = obj_idx[e];
    if (!g_mask[o]) return;
    int ev = evt_idx[e];
    const float4* src = (const float4*)(g_proj + (size_t)ev * OBJ_DIM);
    float* dst = g_sums + (size_t)o * OBJ_DIM;
    float4 v0 = src[lane];
    float4 v1 = src[lane + 32];
    int b0 = lane << 2, b1 = (lane + 32) << 2;
    atomicAdd(dst + b0 + 0, v0.x); atomicAdd(dst + b0 + 1, v0.y);
    atomicAdd(dst + b0 + 2, v0.z); atomicAdd(dst + b0 + 3, v0.w);
    atomicAdd(dst + b1 + 0, v1.x); atomicAdd(dst + b1 + 1, v1.y);
    atomicAdd(dst + b1 + 2, v1.z); atomicAdd(dst + b1 + 3, v1.w);
    if (lane == 0) atomicAdd(&g_cnt[o], 1.0f);
}

__global__ void divide_kernel() {
    int i = blockIdx.x * blockDim.x + threadIdx.x;
    int r = i >> 6;
    if (r >= g_count) return;
    int c = i & 63;
    int o = g_list[r];
    float scale = 1.f / fmaxf(g_cnt[o], 1.f);
    float4* p = (float4*)(g_sums + (size_t)o * OBJ_DIM);
    float4 v = p[c];
    v.x *= scale; v.y *= scale; v.z *= scale; v.w *= scale;
    p[c] = v;
}

__global__ void copy_kernel(const float* __restrict__ x, float* __restrict__ out,
                            int nObj) {
    int i = blockIdx.x * blockDim.x + threadIdx.x;
    if (i < nObj * 64) ((float4*)out)[i] = ((const float4*)x)[i];
}

__device__ __forceinline__ float sigm(float x) { return 1.f / (1.f + expf(-x)); }

__global__ void gru_final_kernel(const float* __restrict__ objX,
                                 float* __restrict__ out, int nMain)
{
    int i = blockIdx.x * blockDim.x + threadIdx.x;
    int r = i >> 6;
    if (r >= g_count) return;
    int c = i & 63;
    int o = g_list[r];
    const float4* gi4 = (const float4*)(g_gi + (size_t)r * GRU3);
    const float4* gh4 = (const float4*)(g_gh + (size_t)r * GRU3);
    float4 ir = gi4[c],        hr = gh4[c];
    float4 iz = gi4[64 + c],   hz = gh4[64 + c];
    float4 in_ = gi4[128 + c], hn = gh4[128 + c];
    float4 h = ((const float4*)(objX + (size_t)o * OBJ_DIM))[c];

    float4 v;
    { float rg = sigm(ir.x + hr.x), z = sigm(iz.x + hz.x);
      float n = tanhf(in_.x + rg * hn.x); v.x = (1.f - z) * n + z * h.x; }
    { float rg = sigm(ir.y + hr.y), z = sigm(iz.y + hz.y);
      float n = tanhf(in_.y + rg * hn.y); v.y = (1.f - z) * n + z * h.y; }
    { float rg = sigm(ir.z + hr.z), z = sigm(iz.z + hz.z);
      float n = tanhf(in_.z + rg * hn.z); v.z = (1.f - z) * n + z * h.z; }
    { float rg = sigm(ir.w + hr.w), z = sigm(iz.w + hz.w);
      float n = tanhf(in_.w + rg * hn.w); v.w = (1.f - z) * n + z * h.w; }
    ((float4*)(out + (size_t)o * OBJ_DIM))[c] = v;
}

// ---------------- launch ----------------------------------------------------
extern "C" void kernel_launch(void* const* d_in, const int* in_sizes, int n_in,
                              void* d_out, int out_size)
{
    const float* object_X = (const float*)d_in[0];
    const float* event_X  = (const float*)d_in[1];
    const int*   lc_obj   = (const int*)d_in[2];
    const int*   lc_evt   = (const int*)d_in[3];
    const int*   main_idx = (const int*)d_in[4];
    const float* W_proj   = (const float*)d_in[5];
    const float* b_proj   = (const float*)d_in[6];
    const float* W_ih     = (const float*)d_in[7];
    const float* b_ih     = (const float*)d_in[8];
    const float* W_hh     = (const float*)d_in[9];
    const float* b_hh     = (const float*)d_in[10];
    float* out = (float*)d_out;

    int nObj  = in_sizes[0] / OBJ_DIM;
    int nEvt  = in_sizes[1] / OBJ_DIM;
    int nEdge = in_sizes[2];
    int nMain = in_sizes[4];

    float *p_proj, *p_sums, *p_gi, *p_gh;
    cudaGetSymbolAddress((void**)&p_proj, g_proj);
    cudaGetSymbolAddress((void**)&p_sums, g_sums);
    cudaGetSymbolAddress((void**)&p_gi,   g_gi);
    cudaGetSymbolAddress((void**)&p_gh,   g_gh);

    cudaFuncSetAttribute(gemm_wmma, cudaFuncAttributeMaxDynamicSharedMemorySize,
                         GEMM_SMEM);

    // 1. init scratch (sums, cnt, mask, count)
    zero_kernel<<<(nObj * 64 + 255) / 256, 256>>>(nObj);
    // 2. mask + compact unique main objects
    mask_kernel<<<(nMain + 255) / 256, 256>>>(main_idx, nMain);
    compact_kernel<<<(nObj + 255) / 256, 256>>>(nObj);
    // 3. per-event projection: proj = relu(event_X @ W_proj^T + b_proj)
    gemm_wmma<<<dim3(2, (nEvt + 127) / 128), 512, GEMM_SMEM>>>(
        event_X, W_proj, b_proj, p_proj, nEvt, OBJ_DIM, OBJ_DIM, 0, 0, 1);
    // 4. masked scatter-mean over edges
    scatter_kernel<<<(nEdge * 32 + 255) / 256, 256>>>(lc_obj, lc_evt, nEdge);
    divide_kernel<<<(nMain * 64 + 255) / 256, 256>>>();
    // 5. GRU input/hidden GEMMs on compacted rows only
    gemm_wmma<<<dim3(6, (nMain + 127) / 128), 512, GEMM_SMEM>>>(
        p_sums, W_ih, b_ih, p_gi, nMain, GRU3, OBJ_DIM, 1, 1, 0);
    gemm_wmma<<<dim3(6, (nMain + 127) / 128), 512, GEMM_SMEM>>>(
        object_X, W_hh, b_hh, p_gh, nMain, GRU3, OBJ_DIM, 1, 1, 0);
    // 6. pass-through copy + fused gate epilogue overwriting main rows
    copy_kernel<<<(nObj * 64 + 255) / 256, 256>>>(object_X, out, nObj);
    gru_final_kernel<<<(nMain * 64 + 255) / 256, 256>>>(object_X, out, nMain);
}

// round 15
// speedup vs baseline: 1.6998x; 1.1007x over previous
#include <cuda_runtime.h>
#include <cuda_bf16.h>
#include <mma.h>
#include <math.h>
#include <stdint.h>

using namespace nvcuda;

#define OBJ_DIM 256
#define GRU3    768
#define MAX_OBJ  50000
#define MAX_EVT  100000
#define MAX_EDGE 500000
#define MAX_MAIN 25000

// ---------------- device scratch (allocation-free per harness rules) --------
__device__ float g_proj[(size_t)MAX_EVT * OBJ_DIM];   // relu(event_X @ Wp^T + bp)
__device__ float g_sums[(size_t)MAX_OBJ * OBJ_DIM];   // profile rows (masked only)
__device__ int   g_mask[MAX_OBJ];
__device__ int   g_list[MAX_MAIN];                    // compacted unique main objs
__device__ int   g_count;
__device__ int   g_deg[MAX_OBJ];                      // masked edge degree
__device__ int   g_cur[MAX_OBJ];                      // fill cursor
__device__ int   g_start[MAX_OBJ + 1];                // CSR offsets
__device__ int   g_elist[MAX_EDGE];                   // event idx per masked edge
__device__ float g_gi[(size_t)MAX_MAIN * GRU3];
__device__ float g_gh[(size_t)MAX_MAIN * GRU3];

// fp32 -> (bf16 hi, bf16 lo) packed pairs (lo = residual, 16 effective bits)
__device__ __forceinline__ void split2(float a, float b, uint32_t& h, uint32_t& l) {
    __nv_bfloat16 ha = __float2bfloat16(a), hb = __float2bfloat16(b);
    float la = a - __bfloat162float(ha);
    float lb = b - __bfloat162float(hb);
    h = (uint32_t)__bfloat16_as_ushort(ha) | ((uint32_t)__bfloat16_as_ushort(hb) << 16);
    __nv_bfloat162 lp = __floats2bfloat162_rn(la, lb);
    l = *reinterpret_cast<uint32_t*>(&lp);
}

// ---------------- WMMA bf16x3 GEMM: C[M,N] = act(A[M,256] @ W[N,256]^T + b) -
// Block 128x128, BK=32, 16 warps (4m x 4n), warp tile 32x32 (2x2 wmma 16x16x16).
// bf16 split: acc += Ah*Bh + Ah*Bl + Al*Bh  (fp32 accumulate).
#define LDA 40                    /* bf16 tile leading dim (80 B, 16B-mult) */
#define TILE_E (128 * LDA)        /* 5120 bf16 per half-tile */
#define BUF_E  (4 * TILE_E)       /* Ah, Al, Bh, Bl */
#define LDE 132                   /* epilogue f32 ldm */
#define GEMM_SMEM 81920           /* 2 x 40960 B buffers; epilogue 67584 fits */

__global__ __launch_bounds__(512, 1) void gemm_wmma(
    const float* __restrict__ A, const float* __restrict__ W,
    const float* __restrict__ bias, float* __restrict__ C,
    int M, int N, int K, int useList, int useCount, int doRelu)
{
    extern __shared__ __align__(128) float smemf[];
    __nv_bfloat16* sB = (__nv_bfloat16*)smemf;

    int Meff = useCount ? g_count : M;
    int row0 = blockIdx.y * 128;
    if (row0 >= Meff) return;
    int n0 = blockIdx.x * 128;

    int t = threadIdx.x;
    int wid = t >> 5;
    int warp_m = wid >> 2, warp_n = wid & 3;

    int lr = t >> 2;
    int lcolg = (t & 3) << 3;
    long arow = -1;
    {
        int g0 = row0 + lr;
        if (g0 < Meff) arow = useList ? (long)g_list[g0] : (long)g0;
    }
    const float* wp = W + (size_t)(n0 + lr) * K;

    wmma::fragment<wmma::accumulator, 16, 16, 16, float> acc[2][2];
#pragma unroll
    for (int i = 0; i < 2; i++)
#pragma unroll
        for (int j = 0; j < 2; j++) wmma::fill_fragment(acc[i][j], 0.0f);

    float4 ax, ay, wx, wy;

    auto loadS = [&](int k0) {
        float4 z = make_float4(0.f, 0.f, 0.f, 0.f);
        if (arow >= 0) {
            const float* p = A + arow * (long)K + k0 + lcolg;
            ax = *(const float4*)p; ay = *(const float4*)(p + 4);
        } else { ax = z; ay = z; }
        wx = *(const float4*)(wp + k0 + lcolg);
        wy = *(const float4*)(wp + k0 + lcolg + 4);
    };
    auto storeS = [&](int buf) {
        __nv_bfloat16* base = sB + buf * BUF_E;
        int off = lr * LDA + lcolg;
        uint32_t h[4], l[4];
        split2(ax.x, ax.y, h[0], l[0]); split2(ax.z, ax.w, h[1], l[1]);
        split2(ay.x, ay.y, h[2], l[2]); split2(ay.z, ay.w, h[3], l[3]);
        *(uint4*)(base + off)          = make_uint4(h[0], h[1], h[2], h[3]);
        *(uint4*)(base + TILE_E + off) = make_uint4(l[0], l[1], l[2], l[3]);
        split2(wx.x, wx.y, h[0], l[0]); split2(wx.z, wx.w, h[1], l[1]);
        split2(wy.x, wy.y, h[2], l[2]); split2(wy.z, wy.w, h[3], l[3]);
        *(uint4*)(base + 2 * TILE_E + off) = make_uint4(h[0], h[1], h[2], h[3]);
        *(uint4*)(base + 3 * TILE_E + off) = make_uint4(l[0], l[1], l[2], l[3]);
    };
    auto compute = [&](int buf) {
        const __nv_bfloat16* Ah = sB + buf * BUF_E;
        const __nv_bfloat16* Al = Ah + TILE_E;
        const __nv_bfloat16* Bh = Ah + 2 * TILE_E;
        const __nv_bfloat16* Bl = Ah + 3 * TILE_E;
#pragma unroll
        for (int kk = 0; kk < 32; kk += 16) {
            wmma::fragment<wmma::matrix_a, 16, 16, 16, __nv_bfloat16,
                           wmma::row_major> ah[2], al[2];
#pragma unroll
            for (int i = 0; i < 2; i++) {
                int r = (warp_m * 32 + i * 16) * LDA + kk;
                wmma::load_matrix_sync(ah[i], Ah + r, LDA);
                wmma::load_matrix_sync(al[i], Al + r, LDA);
            }
#pragma unroll
            for (int j = 0; j < 2; j++) {
                wmma::fragment<wmma::matrix_b, 16, 16, 16, __nv_bfloat16,
                               wmma::col_major> bh, bl;
                int rb = (warp_n * 32 + j * 16) * LDA + kk;
                wmma::load_matrix_sync(bh, Bh + rb, LDA);
                wmma::load_matrix_sync(bl, Bl + rb, LDA);
#pragma unroll
                for (int i = 0; i < 2; i++) {
                    wmma::mma_sync(acc[i][j], ah[i], bh, acc[i][j]);
                    wmma::mma_sync(acc[i][j], ah[i], bl, acc[i][j]);
                    wmma::mma_sync(acc[i][j], al[i], bh, acc[i][j]);
                }
            }
        }
    };

    int nT = K / 32;              // 8
    loadS(0);
    storeS(0);
    __syncthreads();
    int cur = 0;
    for (int kt = 0; kt < nT; kt++) {
        if (kt + 1 < nT) loadS((kt + 1) * 32);
        compute(cur);
        if (kt + 1 < nT) storeS(cur ^ 1);
        __syncthreads();
        cur ^= 1;
    }

    __syncthreads();
#pragma unroll
    for (int i = 0; i < 2; i++)
#pragma unroll
        for (int j = 0; j < 2; j++)
            wmma::store_matrix_sync(
                smemf + (size_t)(warp_m * 32 + i * 16) * LDE + warp_n * 32 + j * 16,
                acc[i][j], LDE, wmma::mem_row_major);
    __syncthreads();
#pragma unroll
    for (int it = 0; it < 8; it++) {
        int idx = t + it * 512;
        int row = idx >> 5;
        int col = (idx & 31) << 2;
        int m = row0 + row;
        if (m >= Meff) continue;
        const float* src = smemf + (size_t)row * LDE + col;
        float4 v = *(const float4*)src;
        float4 bb = *(const float4*)(bias + n0 + col);
        v.x += bb.x; v.y += bb.y; v.z += bb.z; v.w += bb.w;
        if (doRelu) {
            v.x = fmaxf(v.x, 0.f); v.y = fmaxf(v.y, 0.f);
            v.z = fmaxf(v.z, 0.f); v.w = fmaxf(v.w, 0.f);
        }
        *(float4*)(C + (size_t)m * N + n0 + col) = v;
    }
}

// ---------------- small utility kernels -------------------------------------
__global__ void zero_kernel(int nObj) {
    int i = blockIdx.x * blockDim.x + threadIdx.x;
    if (i < nObj) { g_mask[i] = 0; g_deg[i] = 0; g_cur[i] = 0; }
    if (i == 0)   g_count = 0;
}

__global__ void mask_kernel(const int* __restrict__ main_idx, int nMain) {
    int i = blockIdx.x * blockDim.x + threadIdx.x;
    if (i < nMain) g_mask[main_idx[i]] = 1;
}

__global__ void compact_kernel(int nObj) {
    int i = blockIdx.x * blockDim.x + threadIdx.x;
    if (i < nObj && g_mask[i]) {
        int p = atomicAdd(&g_count, 1);
        g_list[p] = i;
    }
}

// CSR build: histogram of masked edges per object
__global__ void hist_kernel(const int* __restrict__ obj_idx, int nEdge) {
    int i = blockIdx.x * blockDim.x + threadIdx.x;
    if (i < nEdge) {
        int o = obj_idx[i];
        if (g_mask[o]) atomicAdd(&g_deg[o], 1);
    }
}

// single-block exclusive scan over g_deg -> g_start (warp-scan based)
__global__ void scan_kernel(int nObj) {
    __shared__ int ws[32];
    __shared__ int carry, tot;
    int tid = threadIdx.x, lane = tid & 31, wid = tid >> 5;
    if (tid == 0) { carry = 0; tot = 0; }
    __syncthreads();
    for (int base = 0; base < nObj; base += 1024) {
        int i = base + tid;
        int v = (i < nObj) ? g_deg[i] : 0;
        int inc = v;
#pragma unroll
        for (int off = 1; off < 32; off <<= 1) {
            int u = __shfl_up_sync(0xFFFFFFFFu, inc, off);
            if (lane >= off) inc += u;
        }
        if (lane == 31) ws[wid] = inc;
        __syncthreads();
        if (wid == 0) {
            int wv = ws[lane];
            int winc = wv;
#pragma unroll
            for (int off = 1; off < 32; off <<= 1) {
                int u = __shfl_up_sync(0xFFFFFFFFu, winc, off);
                if (lane >= off) winc += u;
            }
            ws[lane] = winc - wv;          // exclusive warp offset
            if (lane == 31) tot = winc;    // chunk total
        }
        __syncthreads();
        if (i < nObj) g_start[i] = carry + ws[wid] + inc - v;
        __syncthreads();
        if (tid == 0) carry += tot;
        __syncthreads();
    }
    if (threadIdx.x == 0) g_start[nObj] = carry;
}

// fill CSR edge lists (event index per masked edge)
__global__ void fill_kernel(const int* __restrict__ obj_idx,
                            const int* __restrict__ evt_idx, int nEdge) {
    int i = blockIdx.x * blockDim.x + threadIdx.x;
    if (i < nEdge) {
        int o = obj_idx[i];
        if (g_mask[o]) {
            int p = atomicAdd(&g_cur[o], 1);
            g_elist[g_start[o] + p] = evt_idx[i];
        }
    }
}

// gather-mean: one warp per compacted object, accumulate proj rows, scale, store
__global__ void gather_kernel() {
    int gt   = blockIdx.x * blockDim.x + threadIdx.x;
    int r    = gt >> 5;
    int lane = gt & 31;
    if (r >= g_count) return;
    int o = g_list[r];
    int s = g_start[o];
    int d = g_start[o + 1] - s;
    float4 a0 = make_float4(0.f, 0.f, 0.f, 0.f);
    float4 a1 = a0;
    for (int j = 0; j < d; j++) {
        int ev = g_elist[s + j];
        const float4* src = (const float4*)(g_proj + (size_t)ev * OBJ_DIM);
        float4 v0 = src[lane];
        float4 v1 = src[lane + 32];
        a0.x += v0.x; a0.y += v0.y; a0.z += v0.z; a0.w += v0.w;
        a1.x += v1.x; a1.y += v1.y; a1.z += v1.z; a1.w += v1.w;
    }
    float sc = 1.f / fmaxf((float)d, 1.f);
    float4* dst = (float4*)(g_sums + (size_t)o * OBJ_DIM);
    a0.x *= sc; a0.y *= sc; a0.z *= sc; a0.w *= sc;
    a1.x *= sc; a1.y *= sc; a1.z *= sc; a1.w *= sc;
    dst[lane]      = a0;
    dst[lane + 32] = a1;
}

__global__ void copy_kernel(const float* __restrict__ x, float* __restrict__ out,
                            int nObj) {
    int i = blockIdx.x * blockDim.x + threadIdx.x;
    if (i < nObj * 64) ((float4*)out)[i] = ((const float4*)x)[i];
}

__device__ __forceinline__ float sigm(float x) { return 1.f / (1.f + expf(-x)); }

__global__ void gru_final_kernel(const float* __restrict__ objX,
                                 float* __restrict__ out, int nMain)
{
    int i = blockIdx.x * blockDim.x + threadIdx.x;
    int r = i >> 6;
    if (r >= g_count) return;
    int c = i & 63;
    int o = g_list[r];
    const float4* gi4 = (const float4*)(g_gi + (size_t)r * GRU3);
    const float4* gh4 = (const float4*)(g_gh + (size_t)r * GRU3);
    float4 ir = gi4[c],        hr = gh4[c];
    float4 iz = gi4[64 + c],   hz = gh4[64 + c];
    float4 in_ = gi4[128 + c], hn = gh4[128 + c];
    float4 h = ((const float4*)(objX + (size_t)o * OBJ_DIM))[c];

    float4 v;
    { float rg = sigm(ir.x + hr.x), z = sigm(iz.x + hz.x);
      float n = tanhf(in_.x + rg * hn.x); v.x = (1.f - z) * n + z * h.x; }
    { float rg = sigm(ir.y + hr.y), z = sigm(iz.y + hz.y);
      float n = tanhf(in_.y + rg * hn.y); v.y = (1.f - z) * n + z * h.y; }
    { float rg = sigm(ir.z + hr.z), z = sigm(iz.z + hz.z);
      float n = tanhf(in_.z + rg * hn.z); v.z = (1.f - z) * n + z * h.z; }
    { float rg = sigm(ir.w + hr.w), z = sigm(iz.w + hz.w);
      float n = tanhf(in_.w + rg * hn.w); v.w = (1.f - z) * n + z * h.w; }
    ((float4*)(out + (size_t)o * OBJ_DIM))[c] = v;
}

// ---------------- launch ----------------------------------------------------
extern "C" void kernel_launch(void* const* d_in, const int* in_sizes, int n_in,
                              void* d_out, int out_size)
{
    const float* object_X = (const float*)d_in[0];
    const float* event_X  = (const float*)d_in[1];
    const int*   lc_obj   = (const int*)d_in[2];
    const int*   lc_evt   = (const int*)d_in[3];
    const int*   main_idx = (const int*)d_in[4];
    const float* W_proj   = (const float*)d_in[5];
    const float* b_proj   = (const float*)d_in[6];
    const float* W_ih     = (const float*)d_in[7];
    const float* b_ih     = (const float*)d_in[8];
    const float* W_hh     = (const float*)d_in[9];
    const float* b_hh     = (const float*)d_in[10];
    float* out = (float*)d_out;

    int nObj  = in_sizes[0] / OBJ_DIM;
    int nEvt  = in_sizes[1] / OBJ_DIM;
    int nEdge = in_sizes[2];
    int nMain = in_sizes[4];

    float *p_proj, *p_sums, *p_gi, *p_gh;
    cudaGetSymbolAddress((void**)&p_proj, g_proj);
    cudaGetSymbolAddress((void**)&p_sums, g_sums);
    cudaGetSymbolAddress((void**)&p_gi,   g_gi);
    cudaGetSymbolAddress((void**)&p_gh,   g_gh);

    cudaFuncSetAttribute(gemm_wmma, cudaFuncAttributeMaxDynamicSharedMemorySize,
                         GEMM_SMEM);

    // 1. init scratch (mask, deg, cursor, count)
    zero_kernel<<<(nObj + 255) / 256, 256>>>(nObj);
    // 2. mask + compact unique main objects
    mask_kernel<<<(nMain + 255) / 256, 256>>>(main_idx, nMain);
    compact_kernel<<<(nObj + 255) / 256, 256>>>(nObj);
    // 3. per-event projection: proj = relu(event_X @ W_proj^T + b_proj)
    gemm_wmma<<<dim3(2, (nEvt + 127) / 128), 512, GEMM_SMEM>>>(
        event_X, W_proj, b_proj, p_proj, nEvt, OBJ_DIM, OBJ_DIM, 0, 0, 1);
    // 4. CSR build over masked edges, then gather-mean (no float atomics)
    hist_kernel<<<(nEdge + 255) / 256, 256>>>(lc_obj, nEdge);
    scan_kernel<<<1, 1024>>>(nObj);
    fill_kernel<<<(nEdge + 255) / 256, 256>>>(lc_obj, lc_evt, nEdge);
    gather_kernel<<<(nMain + 7) / 8, 256>>>();
    // 5. GRU input/hidden GEMMs on compacted rows only
    gemm_wmma<<<dim3(6, (nMain + 127) / 128), 512, GEMM_SMEM>>>(
        p_sums, W_ih, b_ih, p_gi, nMain, GRU3, OBJ_DIM, 1, 1, 0);
    gemm_wmma<<<dim3(6, (nMain + 127) / 128), 512, GEMM_SMEM>>>(
        object_X, W_hh, b_hh, p_gh, nMain, GRU3, OBJ_DIM, 1, 1, 0);
    // 6. pass-through copy + fused gate epilogue overwriting main rows
    copy_kernel<<<(nObj * 64 + 255) / 256, 256>>>(object_X, out, nObj);
    gru_final_kernel<<<(nMain * 64 + 255) / 256, 256>>>(object_X, out, nMain);
}

// round 16
// speedup vs baseline: 1.8219x; 1.0718x over previous
#include <cuda_runtime.h>
#include <cuda_bf16.h>
#include <mma.h>
#include <math.h>
#include <stdint.h>

using namespace nvcuda;

#define OBJ_DIM 256
#define GRU3    768
#define MAX_OBJ  50000
#define MAX_EVT  100000
#define MAX_EDGE 500000
#define MAX_MAIN 25000

// ---------------- device scratch (allocation-free per harness rules) --------
__device__ float g_proj[(size_t)MAX_EVT * OBJ_DIM];   // relu(event_X @ Wp^T + bp)
__device__ float g_sums[(size_t)MAX_OBJ * OBJ_DIM];   // profile rows (masked only)
__device__ int   g_mask[MAX_OBJ];
__device__ int   g_list[MAX_MAIN];                    // compacted unique main objs
__device__ int   g_count;
__device__ int   g_deg[MAX_OBJ];                      // masked edge degree
__device__ int   g_cur[MAX_OBJ];                      // fill cursor
__device__ int   g_start[MAX_OBJ + 1];                // CSR offsets
__device__ int   g_elist[MAX_EDGE];                   // event idx per masked edge
__device__ float g_gi[(size_t)MAX_MAIN * GRU3];
__device__ float g_gh[(size_t)MAX_MAIN * GRU3];

// fp32 -> (bf16 hi, bf16 lo) packed pairs (lo = residual, 16 effective bits)
__device__ __forceinline__ void split2(float a, float b, uint32_t& h, uint32_t& l) {
    __nv_bfloat16 ha = __float2bfloat16(a), hb = __float2bfloat16(b);
    float la = a - __bfloat162float(ha);
    float lb = b - __bfloat162float(hb);
    h = (uint32_t)__bfloat16_as_ushort(ha) | ((uint32_t)__bfloat16_as_ushort(hb) << 16);
    __nv_bfloat162 lp = __floats2bfloat162_rn(la, lb);
    l = *reinterpret_cast<uint32_t*>(&lp);
}

// ---------------- WMMA bf16x3 GEMM: C[M,N] = act(A[M,256] @ W[N,256]^T + b) -
// Block 64x128, BK=32, 8 warps (2m x 4n), warp tile 32x32 (2x2 wmma 16x16x16).
// bf16 split: acc += Ah*Bh + Ah*Bl + Al*Bh  (fp32 accumulate).
// 256 threads, 2 CTAs/SM (60KB smem, <=128 regs) so CTA phases overlap.
// gridDim.z selects operand set (fuses the two GRU GEMMs into one launch).
#define LDA 40                    /* bf16 tile leading dim (80 B, 16B-mult) */
#define A_E   (64 * LDA)          /* 2560 bf16: A half-tile */
#define B_E   (128 * LDA)         /* 5120 bf16: B half-tile */
#define OFF_AL (A_E)
#define OFF_BH (2 * A_E)
#define OFF_BL (2 * A_E + B_E)
#define BUF_E  (2 * A_E + 2 * B_E)  /* 15360 elems = 30720 B per buffer */
#define LDE 132                   /* epilogue f32 ldm */
#define GEMM_SMEM 61440           /* 2 buffers; epilogue 64*132*4=33792 fits */

__global__ __launch_bounds__(256, 2) void gemm_wmma(
    const float* __restrict__ A0, const float* __restrict__ W0,
    const float* __restrict__ b0, float* __restrict__ C0,
    const float* __restrict__ A1, const float* __restrict__ W1,
    const float* __restrict__ b1, float* __restrict__ C1,
    int M, int N, int K, int useList, int useCount, int doRelu)
{
    extern __shared__ __align__(128) float smemf[];
    __nv_bfloat16* sB = (__nv_bfloat16*)smemf;

    const float* A    = blockIdx.z ? A1 : A0;
    const float* W    = blockIdx.z ? W1 : W0;
    const float* bias = blockIdx.z ? b1 : b0;
    float*       C    = blockIdx.z ? C1 : C0;

    int Meff = useCount ? g_count : M;
    int row0 = blockIdx.y * 64;
    if (row0 >= Meff) return;
    int n0 = blockIdx.x * 128;

    int t = threadIdx.x;
    int wid = t >> 5;
    int warp_m = wid >> 2, warp_n = wid & 3;   // 2 x 4

    // loader mapping: A row = t>>2 (0..63), 8 cols; W row = t>>1 (0..127), 16 cols
    int lra = t >> 2, lca = (t & 3) << 3;
    int lrw = t >> 1, lcw = (t & 1) << 4;
    long arow = -1;
    {
        int g0 = row0 + lra;
        if (g0 < Meff) arow = useList ? (long)g_list[g0] : (long)g0;
    }
    const float* wp = W + (size_t)(n0 + lrw) * K;

    wmma::fragment<wmma::accumulator, 16, 16, 16, float> acc[2][2];
#pragma unroll
    for (int i = 0; i < 2; i++)
#pragma unroll
        for (int j = 0; j < 2; j++) wmma::fill_fragment(acc[i][j], 0.0f);

    float4 ax, ay, w0, w1, w2, w3;            // staged k-tile (24 floats)

    auto loadS = [&](int k0) {
        float4 z = make_float4(0.f, 0.f, 0.f, 0.f);
        if (arow >= 0) {
            const float* p = A + arow * (long)K + k0 + lca;
            ax = *(const float4*)p; ay = *(const float4*)(p + 4);
        } else { ax = z; ay = z; }
        const float* q = wp + k0 + lcw;
        w0 = *(const float4*)q;        w1 = *(const float4*)(q + 4);
        w2 = *(const float4*)(q + 8);  w3 = *(const float4*)(q + 12);
    };
    auto storeS = [&](int buf) {
        __nv_bfloat16* base = sB + buf * BUF_E;
        uint32_t h[4], l[4];
        int offa = lra * LDA + lca;
        split2(ax.x, ax.y, h[0], l[0]); split2(ax.z, ax.w, h[1], l[1]);
        split2(ay.x, ay.y, h[2], l[2]); split2(ay.z, ay.w, h[3], l[3]);
        *(uint4*)(base + offa)          = make_uint4(h[0], h[1], h[2], h[3]);
        *(uint4*)(base + OFF_AL + offa) = make_uint4(l[0], l[1], l[2], l[3]);
        int offw = lrw * LDA + lcw;
        split2(w0.x, w0.y, h[0], l[0]); split2(w0.z, w0.w, h[1], l[1]);
        split2(w1.x, w1.y, h[2], l[2]); split2(w1.z, w1.w, h[3], l[3]);
        *(uint4*)(base + OFF_BH + offw) = make_uint4(h[0], h[1], h[2], h[3]);
        *(uint4*)(base + OFF_BL + offw) = make_uint4(l[0], l[1], l[2], l[3]);
        split2(w2.x, w2.y, h[0], l[0]); split2(w2.z, w2.w, h[1], l[1]);
        split2(w3.x, w3.y, h[2], l[2]); split2(w3.z, w3.w, h[3], l[3]);
        *(uint4*)(base + OFF_BH + offw + 8) = make_uint4(h[0], h[1], h[2], h[3]);
        *(uint4*)(base + OFF_BL + offw + 8) = make_uint4(l[0], l[1], l[2], l[3]);
    };
    auto compute = [&](int buf) {
        const __nv_bfloat16* Ah = sB + buf * BUF_E;
        const __nv_bfloat16* Al = Ah + OFF_AL;
        const __nv_bfloat16* Bh = Ah + OFF_BH;
        const __nv_bfloat16* Bl = Ah + OFF_BL;
#pragma unroll
        for (int kk = 0; kk < 32; kk += 16) {
            wmma::fragment<wmma::matrix_a, 16, 16, 16, __nv_bfloat16,
                           wmma::row_major> ah[2], al[2];
#pragma unroll
            for (int i = 0; i < 2; i++) {
                int r = (warp_m * 32 + i * 16) * LDA + kk;
                wmma::load_matrix_sync(ah[i], Ah + r, LDA);
                wmma::load_matrix_sync(al[i], Al + r, LDA);
            }
#pragma unroll
            for (int j = 0; j < 2; j++) {
                wmma::fragment<wmma::matrix_b, 16, 16, 16, __nv_bfloat16,
                               wmma::col_major> bh, bl;
                int rb = (warp_n * 32 + j * 16) * LDA + kk;
                wmma::load_matrix_sync(bh, Bh + rb, LDA);
                wmma::load_matrix_sync(bl, Bl + rb, LDA);
#pragma unroll
                for (int i = 0; i < 2; i++) {
                    wmma::mma_sync(acc[i][j], ah[i], bh, acc[i][j]);
                    wmma::mma_sync(acc[i][j], ah[i], bl, acc[i][j]);
                    wmma::mma_sync(acc[i][j], al[i], bh, acc[i][j]);
                }
            }
        }
    };

    int nT = K / 32;              // 8
    loadS(0);
    storeS(0);
    __syncthreads();
    int cur = 0;
    for (int kt = 0; kt < nT; kt++) {
        if (kt + 1 < nT) loadS((kt + 1) * 32);
        compute(cur);
        if (kt + 1 < nT) storeS(cur ^ 1);
        __syncthreads();
        cur ^= 1;
    }

    // epilogue: acc frags -> smem (f32, [64][LDE]) -> bias/relu -> C
    __syncthreads();
#pragma unroll
    for (int i = 0; i < 2; i++)
#pragma unroll
        for (int j = 0; j < 2; j++)
            wmma::store_matrix_sync(
                smemf + (size_t)(warp_m * 32 + i * 16) * LDE + warp_n * 32 + j * 16,
                acc[i][j], LDE, wmma::mem_row_major);
    __syncthreads();
#pragma unroll
    for (int it = 0; it < 8; it++) {
        int idx = t + it * 256;           // 0..2047
        int row = idx >> 5;               // 0..63
        int col = (idx & 31) << 2;        // 0..124
        int m = row0 + row;
        if (m >= Meff) continue;
        const float* src = smemf + (size_t)row * LDE + col;
        float4 v = *(const float4*)src;
        float4 bb = *(const float4*)(bias + n0 + col);
        v.x += bb.x; v.y += bb.y; v.z += bb.z; v.w += bb.w;
        if (doRelu) {
            v.x = fmaxf(v.x, 0.f); v.y = fmaxf(v.y, 0.f);
            v.z = fmaxf(v.z, 0.f); v.w = fmaxf(v.w, 0.f);
        }
        *(float4*)(C + (size_t)m * N + n0 + col) = v;
    }
}

// ---------------- small utility kernels -------------------------------------
__global__ void zero_kernel(int nObj) {
    int i = blockIdx.x * blockDim.x + threadIdx.x;
    if (i < nObj) { g_mask[i] = 0; g_deg[i] = 0; g_cur[i] = 0; }
    if (i == 0)   g_count = 0;
}

__global__ void mask_kernel(const int* __restrict__ main_idx, int nMain) {
    int i = blockIdx.x * blockDim.x + threadIdx.x;
    if (i < nMain) g_mask[main_idx[i]] = 1;
}

__global__ void compact_kernel(int nObj) {
    int i = blockIdx.x * blockDim.x + threadIdx.x;
    if (i < nObj && g_mask[i]) {
        int p = atomicAdd(&g_count, 1);
        g_list[p] = i;
    }
}

// CSR build: histogram of masked edges per object
__global__ void hist_kernel(const int* __restrict__ obj_idx, int nEdge) {
    int i = blockIdx.x * blockDim.x + threadIdx.x;
    if (i < nEdge) {
        int o = obj_idx[i];
        if (g_mask[o]) atomicAdd(&g_deg[o], 1);
    }
}

// single-block exclusive scan over g_deg -> g_start (warp-scan based)
__global__ void scan_kernel(int nObj) {
    __shared__ int ws[32];
    __shared__ int carry, tot;
    int tid = threadIdx.x, lane = tid & 31, wid = tid >> 5;
    if (tid == 0) { carry = 0; tot = 0; }
    __syncthreads();
    for (int base = 0; base < nObj; base += 1024) {
        int i = base + tid;
        int v = (i < nObj) ? g_deg[i] : 0;
        int inc = v;
#pragma unroll
        for (int off = 1; off < 32; off <<= 1) {
            int u = __shfl_up_sync(0xFFFFFFFFu, inc, off);
            if (lane >= off) inc += u;
        }
        if (lane == 31) ws[wid] = inc;
        __syncthreads();
        if (wid == 0) {
            int wv = ws[lane];
            int winc = wv;
#pragma unroll
            for (int off = 1; off < 32; off <<= 1) {
                int u = __shfl_up_sync(0xFFFFFFFFu, winc, off);
                if (lane >= off) winc += u;
            }
            ws[lane] = winc - wv;          // exclusive warp offset
            if (lane == 31) tot = winc;    // chunk total
        }
        __syncthreads();
        if (i < nObj) g_start[i] = carry + ws[wid] + inc - v;
        __syncthreads();
        if (tid == 0) carry += tot;
        __syncthreads();
    }
    if (threadIdx.x == 0) g_start[nObj] = carry;
}

// fill CSR edge lists (event index per masked edge)
__global__ void fill_kernel(const int* __restrict__ obj_idx,
                            const int* __restrict__ evt_idx, int nEdge) {
    int i = blockIdx.x * blockDim.x + threadIdx.x;
    if (i < nEdge) {
        int o = obj_idx[i];
        if (g_mask[o]) {
            int p = atomicAdd(&g_cur[o], 1);
            g_elist[g_start[o] + p] = evt_idx[i];
        }
    }
}

// gather-mean: one warp per compacted object, accumulate proj rows, scale, store
__global__ void gather_kernel() {
    int gt   = blockIdx.x * blockDim.x + threadIdx.x;
    int r    = gt >> 5;
    int lane = gt & 31;
    if (r >= g_count) return;
    int o = g_list[r];
    int s = g_start[o];
    int d = g_start[o + 1] - s;
    float4 a0 = make_float4(0.f, 0.f, 0.f, 0.f);
    float4 a1 = a0;
    for (int j = 0; j < d; j++) {
        int ev = g_elist[s + j];
        const float4* src = (const float4*)(g_proj + (size_t)ev * OBJ_DIM);
        float4 v0 = src[lane];
        float4 v1 = src[lane + 32];
        a0.x += v0.x; a0.y += v0.y; a0.z += v0.z; a0.w += v0.w;
        a1.x += v1.x; a1.y += v1.y; a1.z += v1.z; a1.w += v1.w;
    }
    float sc = 1.f / fmaxf((float)d, 1.f);
    float4* dst = (float4*)(g_sums + (size_t)o * OBJ_DIM);
    a0.x *= sc; a0.y *= sc; a0.z *= sc; a0.w *= sc;
    a1.x *= sc; a1.y *= sc; a1.z *= sc; a1.w *= sc;
    dst[lane]      = a0;
    dst[lane + 32] = a1;
}

__global__ void copy_kernel(const float* __restrict__ x, float* __restrict__ out,
                            int nObj) {
    int i = blockIdx.x * blockDim.x + threadIdx.x;
    if (i < nObj * 64) ((float4*)out)[i] = ((const float4*)x)[i];
}

__device__ __forceinline__ float sigm(float x) { return 1.f / (1.f + expf(-x)); }

__global__ void gru_final_kernel(const float* __restrict__ objX,
                                 float* __restrict__ out, int nMain)
{
    int i = blockIdx.x * blockDim.x + threadIdx.x;
    int r = i >> 6;
    if (r >= g_count) return;
    int c = i & 63;
    int o = g_list[r];
    const float4* gi4 = (const float4*)(g_gi + (size_t)r * GRU3);
    const float4* gh4 = (const float4*)(g_gh + (size_t)r * GRU3);
    float4 ir = gi4[c],        hr = gh4[c];
    float4 iz = gi4[64 + c],   hz = gh4[64 + c];
    float4 in_ = gi4[128 + c], hn = gh4[128 + c];
    float4 h = ((const float4*)(objX + (size_t)o * OBJ_DIM))[c];

    float4 v;
    { float rg = sigm(ir.x + hr.x), z = sigm(iz.x + hz.x);
      float n = tanhf(in_.x + rg * hn.x); v.x = (1.f - z) * n + z * h.x; }
    { float rg = sigm(ir.y + hr.y), z = sigm(iz.y + hz.y);
      float n = tanhf(in_.y + rg * hn.y); v.y = (1.f - z) * n + z * h.y; }
    { float rg = sigm(ir.z + hr.z), z = sigm(iz.z + hz.z);
      float n = tanhf(in_.z + rg * hn.z); v.z = (1.f - z) * n + z * h.z; }
    { float rg = sigm(ir.w + hr.w), z = sigm(iz.w + hz.w);
      float n = tanhf(in_.w + rg * hn.w); v.w = (1.f - z) * n + z * h.w; }
    ((float4*)(out + (size_t)o * OBJ_DIM))[c] = v;
}

// ---------------- launch ----------------------------------------------------
extern "C" void kernel_launch(void* const* d_in, const int* in_sizes, int n_in,
                              void* d_out, int out_size)
{
    const float* object_X = (const float*)d_in[0];
    const float* event_X  = (const float*)d_in[1];
    const int*   lc_obj   = (const int*)d_in[2];
    const int*   lc_evt   = (const int*)d_in[3];
    const int*   main_idx = (const int*)d_in[4];
    const float* W_proj   = (const float*)d_in[5];
    const float* b_proj   = (const float*)d_in[6];
    const float* W_ih     = (const float*)d_in[7];
    const float* b_ih     = (const float*)d_in[8];
    const float* W_hh     = (const float*)d_in[9];
    const float* b_hh     = (const float*)d_in[10];
    float* out = (float*)d_out;

    int nObj  = in_sizes[0] / OBJ_DIM;
    int nEvt  = in_sizes[1] / OBJ_DIM;
    int nEdge = in_sizes[2];
    int nMain = in_sizes[4];

    float *p_proj, *p_sums, *p_gi, *p_gh;
    cudaGetSymbolAddress((void**)&p_proj, g_proj);
    cudaGetSymbolAddress((void**)&p_sums, g_sums);
    cudaGetSymbolAddress((void**)&p_gi,   g_gi);
    cudaGetSymbolAddress((void**)&p_gh,   g_gh);

    cudaFuncSetAttribute(gemm_wmma, cudaFuncAttributeMaxDynamicSharedMemorySize,
                         GEMM_SMEM);

    // 1. init scratch (mask, deg, cursor, count)
    zero_kernel<<<(nObj + 255) / 256, 256>>>(nObj);
    // 2. mask + compact unique main objects
    mask_kernel<<<(nMain + 255) / 256, 256>>>(main_idx, nMain);
    compact_kernel<<<(nObj + 255) / 256, 256>>>(nObj);
    // 3. per-event projection: proj = relu(event_X @ W_proj^T + b_proj)
    gemm_wmma<<<dim3(2, (nEvt + 63) / 64, 1), 256, GEMM_SMEM>>>(
        event_X, W_proj, b_proj, p_proj,
        event_X, W_proj, b_proj, p_proj,
        nEvt, OBJ_DIM, OBJ_DIM, 0, 0, 1);
    // 4. CSR build over masked edges, then gather-mean (no float atomics)
    hist_kernel<<<(nEdge + 255) / 256, 256>>>(lc_obj, nEdge);
    scan_kernel<<<1, 1024>>>(nObj);
    fill_kernel<<<(nEdge + 255) / 256, 256>>>(lc_obj, lc_evt, nEdge);
    gather_kernel<<<(nMain + 7) / 8, 256>>>();
    // 5. GRU input+hidden GEMMs fused into one launch (z selects operands)
    gemm_wmma<<<dim3(6, (nMain + 63) / 64, 2), 256, GEMM_SMEM>>>(
        p_sums, W_ih, b_ih, p_gi,
        object_X, W_hh, b_hh, p_gh,
        nMain, GRU3, OBJ_DIM, 1, 1, 0);
    // 6. pass-through copy + fused gate epilogue overwriting main rows
    copy_kernel<<<(nObj * 64 + 255) / 256, 256>>>(object_X, out, nObj);
    gru_final_kernel<<<(nMain * 64 + 255) / 256, 256>>>(object_X, out, nMain);
}